// round 9
// baseline (speedup 1.0000x reference)
#include <cuda_runtime.h>
#include <math.h>

// Problem constants
#define BB 16
#define HH 16
#define NN 577
#define DD 64
#define CC 1024
#define MTOK (BB*NN)            // 9232
#define PLANE (BB*HH*NN*DD)     // 9,453,568 floats per q/k/v plane
#define OUT_ELEMS (MTOK*CC)     // 9,453,568
#define CTA_OFS OUT_ELEMS
#define CTL_OFS (OUT_ELEMS + MTOK)
#define QSCALE 0.125f           // 1/sqrt(64)

// Scratch (device globals: allocation-free per harness rules)
__device__ float g_qkv[3u * PLANE];       // [3][B][H][N][D], q pre-scaled
__device__ float g_attn[OUT_ELEMS];       // [B][N][C] attention output
__device__ float g_cls_logits[BB*HH*NN];  // per-head CLS-row logits
__device__ float g_cls_max[BB*HH];
__device__ float g_cls_den[BB*HH];

__device__ __forceinline__ unsigned int f2tf32(float f) {
    unsigned int r;
    asm("cvt.rna.tf32.f32 %0, %1;" : "=r"(r) : "f"(f));
    return r;
}

#define MMA_TF32(d, a, b) \
    asm("mma.sync.aligned.m16n8k8.row.col.f32.tf32.tf32.f32 " \
        "{%0,%1,%2,%3}, {%4,%5,%6,%7}, {%8,%9}, {%0,%1,%2,%3};" \
        : "+f"((d)[0]), "+f"((d)[1]), "+f"((d)[2]), "+f"((d)[3]) \
        : "r"((a)[0]), "r"((a)[1]), "r"((a)[2]), "r"((a)[3]), \
          "r"((b)[0]), "r"((b)[1]))

// ---------------------------------------------------------------------------
// tf32 tensor-core GEMM with register-prefetch pipelining.
// C[m,n] = sum_k A[m,k] * W[n,k] (+bias). K = 1024.
// BM=BN=128, BK=32, 256 threads (8 warps as 4m x 2n, warp tile 32x64).
// Global loads for tile k0+32 are issued BEFORE the MMAs of tile k0, so LDG
// latency overlaps tensor work.
// mode 1: QKV epilogue -> scatter into g_qkv (q scaled)
// mode 2: A taken from g_attn, plain epilogue into Cout
// ---------------------------------------------------------------------------
#define GSTRIDE 36   // smem row stride in words: bank = row*4+col -> conflict-free

__global__ __launch_bounds__(256) void mma_gemm_nt(
    const float* __restrict__ A, const float* __restrict__ W,
    const float* __restrict__ bias, float* __restrict__ Cout,
    int M, int N, int mode)
{
    __shared__ unsigned int As[128 * GSTRIDE];
    __shared__ unsigned int Ws[128 * GSTRIDE];
    const int K = 1024;

    const float* Abase = (mode == 2) ? g_attn : A;

    const int tid  = threadIdx.x;
    const int lane = tid & 31;
    const int warp = tid >> 5;
    const int wm   = warp & 3;     // warp row (m): 0..3 -> 32 rows each
    const int wn   = warp >> 2;    // warp col (n): 0..1 -> 64 cols each
    const int bm   = blockIdx.y * 128;
    const int bn   = blockIdx.x * 128;

    float acc[2][8][4];
    #pragma unroll
    for (int i = 0; i < 2; i++)
        #pragma unroll
        for (int j = 0; j < 8; j++)
            #pragma unroll
            for (int e = 0; e < 4; e++) acc[i][j][e] = 0.f;

    const int g  = lane >> 2;      // group id 0..7
    const int tg = lane & 3;       // thread in group 0..3

    // per-thread load coordinates (row, float4-column)
    int lrow[4], lc4[4];
    const float* aptr[4];
    const float* wptr[4];
    bool aval[4];
    #pragma unroll
    for (int i = 0; i < 4; i++) {
        int p   = i * 256 + tid;
        lrow[i] = p >> 3;
        lc4[i]  = (p & 7) << 2;
        int ar  = bm + lrow[i];
        aval[i] = ar < M;
        aptr[i] = Abase + (size_t)(aval[i] ? ar : (M - 1)) * K + lc4[i];
        wptr[i] = W + (size_t)(bn + lrow[i]) * K + lc4[i];
    }

    float4 av[4], wv[4];
    #pragma unroll
    for (int i = 0; i < 4; i++) {
        av[i] = aval[i] ? *(const float4*)(aptr[i]) : make_float4(0.f,0.f,0.f,0.f);
        wv[i] = *(const float4*)(wptr[i]);
    }

    for (int k0 = 0; k0 < K; k0 += 32) {
        __syncthreads();   // previous tile's smem reads complete
        #pragma unroll
        for (int i = 0; i < 4; i++) {
            *(uint4*)(As + lrow[i] * GSTRIDE + lc4[i]) =
                make_uint4(f2tf32(av[i].x), f2tf32(av[i].y), f2tf32(av[i].z), f2tf32(av[i].w));
            *(uint4*)(Ws + lrow[i] * GSTRIDE + lc4[i]) =
                make_uint4(f2tf32(wv[i].x), f2tf32(wv[i].y), f2tf32(wv[i].z), f2tf32(wv[i].w));
        }
        __syncthreads();

        // issue next tile's global loads early (overlap with MMAs)
        if (k0 + 32 < K) {
            #pragma unroll
            for (int i = 0; i < 4; i++) {
                av[i] = aval[i] ? *(const float4*)(aptr[i] + k0 + 32)
                                : make_float4(0.f,0.f,0.f,0.f);
                wv[i] = *(const float4*)(wptr[i] + k0 + 32);
            }
        }

        #pragma unroll
        for (int ks = 0; ks < 4; ks++) {
            const int kb = ks << 3;
            unsigned int af[2][4], bf[8][2];
            #pragma unroll
            for (int mt = 0; mt < 2; mt++) {
                int r0 = wm * 32 + mt * 16 + g;
                af[mt][0] = As[r0 * GSTRIDE + kb + tg];
                af[mt][1] = As[(r0 + 8) * GSTRIDE + kb + tg];
                af[mt][2] = As[r0 * GSTRIDE + kb + tg + 4];
                af[mt][3] = As[(r0 + 8) * GSTRIDE + kb + tg + 4];
            }
            #pragma unroll
            for (int nt = 0; nt < 8; nt++) {
                int nr = wn * 64 + nt * 8 + g;
                bf[nt][0] = Ws[nr * GSTRIDE + kb + tg];
                bf[nt][1] = Ws[nr * GSTRIDE + kb + tg + 4];
            }
            #pragma unroll
            for (int mt = 0; mt < 2; mt++)
                #pragma unroll
                for (int nt = 0; nt < 8; nt++)
                    MMA_TF32(acc[mt][nt], af[mt], bf[nt]);
        }
    }

    // Epilogue. c-elem e: row += (e>=2)*8, col = tg*2 + (e&1)
    #pragma unroll
    for (int mt = 0; mt < 2; mt++) {
        #pragma unroll
        for (int eh = 0; eh < 2; eh++) {          // half: rows g / g+8
            int m = bm + wm * 32 + mt * 16 + g + eh * 8;
            if (m >= M) continue;
            if (mode == 1) {
                int b_  = m / NN;
                int tok = m - b_ * NN;
                #pragma unroll
                for (int nt = 0; nt < 8; nt++) {
                    #pragma unroll
                    for (int ec = 0; ec < 2; ec++) {
                        int n = bn + wn * 64 + nt * 8 + tg * 2 + ec;
                        float v = acc[mt][nt][eh * 2 + ec] + bias[n];
                        int which = n >> 10;
                        int rest  = n & 1023;
                        int h = rest >> 6;
                        int d = rest & 63;
                        if (which == 0) v *= QSCALE;
                        g_qkv[(size_t)which * PLANE + (((size_t)(b_ * HH + h) * NN + tok) << 6) + d] = v;
                    }
                }
            } else {
                #pragma unroll
                for (int nt = 0; nt < 8; nt++) {
                    int n = bn + wn * 64 + nt * 8 + tg * 2;
                    float2 v = make_float2(acc[mt][nt][eh * 2 + 0] + bias[n],
                                           acc[mt][nt][eh * 2 + 1] + bias[n + 1]);
                    *(float2*)(Cout + (size_t)m * N + n) = v;
                }
            }
        }
    }
}

// ---------------------------------------------------------------------------
// Tensor-core flash attention (tf32 mma) with K/V register prefetch.
// Grid (5 q-tiles of 128, 256 bh), 256 threads = 8 warps x 16 q-rows.
// ---------------------------------------------------------------------------
#define FA_SROW 68
#define FA_BQ   128
#define FA_SMEM ((FA_BQ*FA_SROW + 64*FA_SROW + 64*FA_SROW + FA_BQ*FA_SROW) * 4)

__global__ __launch_bounds__(256) void flash_mma_kernel()
{
    extern __shared__ unsigned int smu[];
    unsigned int* Qs = smu;                      // [128][68] tf32
    unsigned int* Ks = Qs + FA_BQ * FA_SROW;     // [64][68]  tf32
    unsigned int* Vs = Ks + 64 * FA_SROW;        // [64][68]  tf32
    unsigned int* Ps = Vs + 64 * FA_SROW;        // [128][68] tf32

    const int tid  = threadIdx.x;
    const int lane = tid & 31;
    const int warp = tid >> 5;
    const int g    = lane >> 2;
    const int tg   = lane & 3;
    const int qt   = blockIdx.x;          // 0..4
    const int bh   = blockIdx.y;          // 0..255
    const int q0g  = qt * FA_BQ;
    const int wr   = warp * 16;           // warp's q-row base in tile

    const float* Qg = g_qkv + (size_t)bh * NN * DD;
    const float* Kg = g_qkv + (size_t)PLANE + (size_t)bh * NN * DD;
    const float* Vg = g_qkv + 2u * (size_t)PLANE + (size_t)bh * NN * DD;

    // Load Q tile (tf32). 128 rows x 16 float4 = 2048, 8 per thread.
    #pragma unroll
    for (int i = 0; i < 8; i++) {
        int p   = i * 256 + tid;
        int row = p >> 4;
        int c4  = (p & 15) << 2;
        int tok = q0g + row; if (tok > NN - 1) tok = NN - 1;   // clamp (rows >= NN unused)
        float4 v = *(const float4*)(Qg + (size_t)tok * DD + c4);
        *(uint4*)(Qs + row * FA_SROW + c4) =
            make_uint4(f2tf32(v.x), f2tf32(v.y), f2tf32(v.z), f2tf32(v.w));
    }

    // per-thread K/V load coords
    int krow[4], kc4[4];
    #pragma unroll
    for (int i = 0; i < 4; i++) {
        int p   = i * 256 + tid;
        krow[i] = p >> 4;
        kc4[i]  = (p & 15) << 2;
    }

    float4 kv[4], vv[4];
    #pragma unroll
    for (int i = 0; i < 4; i++) {
        int tok = krow[i]; if (tok > NN - 1) tok = NN - 1;
        kv[i] = *(const float4*)(Kg + (size_t)tok * DD + kc4[i]);
        vv[i] = *(const float4*)(Vg + (size_t)tok * DD + kc4[i]);
    }

    float oacc[8][4];
    #pragma unroll
    for (int nt = 0; nt < 8; nt++)
        #pragma unroll
        for (int e = 0; e < 4; e++) oacc[nt][e] = 0.f;
    float m_i[2] = { -1e30f, -1e30f };
    float l_i[2] = { 0.f, 0.f };

    for (int kt = 0; kt < 10; kt++) {
        const int k0g = kt * 64;
        __syncthreads();   // prior-iteration Ks/Vs reads complete (also covers Q store)

        #pragma unroll
        for (int i = 0; i < 4; i++) {
            *(uint4*)(Ks + krow[i] * FA_SROW + kc4[i]) =
                make_uint4(f2tf32(kv[i].x), f2tf32(kv[i].y), f2tf32(kv[i].z), f2tf32(kv[i].w));
            *(uint4*)(Vs + krow[i] * FA_SROW + kc4[i]) =
                make_uint4(f2tf32(vv[i].x), f2tf32(vv[i].y), f2tf32(vv[i].z), f2tf32(vv[i].w));
        }
        __syncthreads();

        // prefetch next K/V tile (overlaps with S MMA + softmax + PV MMA)
        if (kt + 1 < 10) {
            int nk0 = (kt + 1) * 64;
            #pragma unroll
            for (int i = 0; i < 4; i++) {
                int tok = nk0 + krow[i]; if (tok > NN - 1) tok = NN - 1;
                kv[i] = *(const float4*)(Kg + (size_t)tok * DD + kc4[i]);
                vv[i] = *(const float4*)(Vg + (size_t)tok * DD + kc4[i]);
            }
        }

        // ---- S = Q K^T : 16 q-rows x 64 keys per warp ----
        float sacc[8][4];
        #pragma unroll
        for (int nt = 0; nt < 8; nt++)
            #pragma unroll
            for (int e = 0; e < 4; e++) sacc[nt][e] = 0.f;

        #pragma unroll
        for (int ks = 0; ks < 8; ks++) {
            const int kb = ks << 3;
            unsigned int af[4], bf[8][2];
            af[0] = Qs[(wr + g) * FA_SROW + kb + tg];
            af[1] = Qs[(wr + g + 8) * FA_SROW + kb + tg];
            af[2] = Qs[(wr + g) * FA_SROW + kb + tg + 4];
            af[3] = Qs[(wr + g + 8) * FA_SROW + kb + tg + 4];
            #pragma unroll
            for (int nt = 0; nt < 8; nt++) {
                bf[nt][0] = Ks[(nt * 8 + g) * FA_SROW + kb + tg];
                bf[nt][1] = Ks[(nt * 8 + g) * FA_SROW + kb + tg + 4];
            }
            #pragma unroll
            for (int nt = 0; nt < 8; nt++)
                MMA_TF32(sacc[nt], af, bf[nt]);
        }

        // ---- online softmax on fragments (rows wr+g and wr+g+8) ----
        #pragma unroll
        for (int eh = 0; eh < 2; eh++) {
            float mloc = -1e30f;
            #pragma unroll
            for (int nt = 0; nt < 8; nt++) {
                #pragma unroll
                for (int ec = 0; ec < 2; ec++) {
                    int key = k0g + nt * 8 + tg * 2 + ec;
                    if (key >= NN) sacc[nt][eh * 2 + ec] = -1e30f;
                    mloc = fmaxf(mloc, sacc[nt][eh * 2 + ec]);
                }
            }
            mloc = fmaxf(mloc, __shfl_xor_sync(0xffffffffu, mloc, 1));
            mloc = fmaxf(mloc, __shfl_xor_sync(0xffffffffu, mloc, 2));
            float m_new = fmaxf(m_i[eh], mloc);
            float alpha = __expf(m_i[eh] - m_new);

            float psum = 0.f;
            int prow = (wr + g + eh * 8) * FA_SROW;
            #pragma unroll
            for (int nt = 0; nt < 8; nt++) {
                float p0 = __expf(sacc[nt][eh * 2 + 0] - m_new);
                float p1 = __expf(sacc[nt][eh * 2 + 1] - m_new);
                psum += p0 + p1;
                *(uint2*)(Ps + prow + nt * 8 + tg * 2) = make_uint2(f2tf32(p0), f2tf32(p1));
            }
            psum += __shfl_xor_sync(0xffffffffu, psum, 1);
            psum += __shfl_xor_sync(0xffffffffu, psum, 2);
            l_i[eh] = l_i[eh] * alpha + psum;
            m_i[eh] = m_new;
            #pragma unroll
            for (int nt = 0; nt < 8; nt++) {
                oacc[nt][eh * 2 + 0] *= alpha;
                oacc[nt][eh * 2 + 1] *= alpha;
            }
        }
        __syncwarp();   // Ps strip visible within warp

        // ---- O += P V : A = P (own strip), B = Vs rows j, cols d ----
        #pragma unroll
        for (int ks = 0; ks < 8; ks++) {
            const int kb = ks << 3;     // key j block
            unsigned int af[4], bf[8][2];
            af[0] = Ps[(wr + g) * FA_SROW + kb + tg];
            af[1] = Ps[(wr + g + 8) * FA_SROW + kb + tg];
            af[2] = Ps[(wr + g) * FA_SROW + kb + tg + 4];
            af[3] = Ps[(wr + g + 8) * FA_SROW + kb + tg + 4];
            #pragma unroll
            for (int nt = 0; nt < 8; nt++) {
                bf[nt][0] = Vs[(kb + tg) * FA_SROW + nt * 8 + g];
                bf[nt][1] = Vs[(kb + tg + 4) * FA_SROW + nt * 8 + g];
            }
            #pragma unroll
            for (int nt = 0; nt < 8; nt++)
                MMA_TF32(oacc[nt], af, bf[nt]);
        }
        __syncwarp();   // Ps reads done before next-iter overwrite
    }

    // ---- write O ----
    const int b_ = bh >> 4, h = bh & 15;
    #pragma unroll
    for (int eh = 0; eh < 2; eh++) {
        int tok = q0g + wr + g + eh * 8;
        if (tok >= NN) continue;
        float inv = 1.f / l_i[eh];
        float* o = g_attn + ((size_t)b_ * NN + tok) * CC + h * DD;
        #pragma unroll
        for (int nt = 0; nt < 8; nt++) {
            float2 v = make_float2(oacc[nt][eh * 2 + 0] * inv,
                                   oacc[nt][eh * 2 + 1] * inv);
            *(float2*)(o + nt * 8 + tg * 2) = v;
        }
    }
}

// ---------------------------------------------------------------------------
// CLS-row logits per (b,h): logits[m] = q0 . k[m]; also max & softmax denom
// ---------------------------------------------------------------------------
__global__ __launch_bounds__(128) void cls_logits_kernel()
{
    __shared__ float q0s[64];
    __shared__ float red[128];
    const int bh  = blockIdx.x;
    const int tid = threadIdx.x;
    const float* Qg = g_qkv + (size_t)bh * NN * DD;            // q already scaled
    const float* Kg = g_qkv + (size_t)PLANE + (size_t)bh * NN * DD;

    if (tid < 64) q0s[tid] = Qg[tid];
    __syncthreads();

    float lg[5];
    float mloc = -1e30f;
    #pragma unroll
    for (int i = 0; i < 5; i++) {
        int m = tid + i*128;
        float s = -1e30f;
        if (m < NN) {
            s = 0.f;
            const float* kr = Kg + (size_t)m * DD;
            #pragma unroll
            for (int d4 = 0; d4 < 64; d4 += 4) {
                float4 k4 = *(const float4*)(kr + d4);
                s += q0s[d4]*k4.x + q0s[d4+1]*k4.y + q0s[d4+2]*k4.z + q0s[d4+3]*k4.w;
            }
            g_cls_logits[(size_t)bh * NN + m] = s;
        }
        lg[i] = s;
        mloc = fmaxf(mloc, s);
    }

    red[tid] = mloc; __syncthreads();
    for (int o = 64; o > 0; o >>= 1) {
        if (tid < o) red[tid] = fmaxf(red[tid], red[tid+o]);
        __syncthreads();
    }
    float mx = red[0];
    __syncthreads();

    float se = 0.f;
    #pragma unroll
    for (int i = 0; i < 5; i++)
        if (lg[i] > -1e29f) se += __expf(lg[i] - mx);
    red[tid] = se; __syncthreads();
    for (int o = 64; o > 0; o >>= 1) {
        if (tid < o) red[tid] += red[tid+o];
        __syncthreads();
    }
    if (tid == 0) { g_cls_max[bh] = mx; g_cls_den[bh] = red[0]; }
}

// Head-mean of CLS logits and CLS attention
__global__ void cls_out_kernel(float* __restrict__ out_cta, float* __restrict__ out_ctl)
{
    int idx = blockIdx.x * blockDim.x + threadIdx.x;
    if (idx >= MTOK) return;
    int b_ = idx / NN;
    int m  = idx - b_ * NN;
    float sl = 0.f, sa = 0.f;
    #pragma unroll
    for (int h = 0; h < HH; h++) {
        int bh = b_ * HH + h;
        float l = g_cls_logits[(size_t)bh * NN + m];
        sl += l;
        sa += __expf(l - g_cls_max[bh]) / g_cls_den[bh];
    }
    out_ctl[idx] = sl * (1.f / 16.f);
    out_cta[idx] = sa * (1.f / 16.f);
}

// ---------------------------------------------------------------------------
extern "C" void kernel_launch(void* const* d_in, const int* in_sizes, int n_in,
                              void* d_out, int out_size)
{
    const float* x      = (const float*)d_in[0];
    const float* w_qkv  = (const float*)d_in[1];
    const float* b_qkv  = (const float*)d_in[2];
    const float* w_proj = (const float*)d_in[3];
    const float* b_proj = (const float*)d_in[4];
    float* out = (float*)d_out;

    // 1) QKV projection + scatter (q scaled) — tf32 tensor cores
    {
        dim3 grid(3*CC/128, (MTOK + 127) / 128);
        mma_gemm_nt<<<grid, 256>>>(x, w_qkv, b_qkv, nullptr, MTOK, 3*CC, 1);
    }

    // 2) Flash attention — tf32 tensor cores
    cudaFuncSetAttribute(flash_mma_kernel,
                         cudaFuncAttributeMaxDynamicSharedMemorySize, FA_SMEM);
    {
        dim3 grid((NN + FA_BQ - 1) / FA_BQ, BB*HH);   // (5, 256)
        flash_mma_kernel<<<grid, 256, FA_SMEM>>>();
    }

    // 3) CLS-row outputs (full fp32)
    cls_logits_kernel<<<BB*HH, 128>>>();
    cls_out_kernel<<<(MTOK + 255) / 256, 256>>>(out + CTA_OFS, out + CTL_OFS);

    // 4) Output projection — tf32 tensor cores
    {
        dim3 grid(CC/128, (MTOK + 127) / 128);
        mma_gemm_nt<<<grid, 256>>>(nullptr, w_proj, b_proj, out, MTOK, CC, 2);
    }
}

// round 10
// speedup vs baseline: 1.1416x; 1.1416x over previous
#include <cuda_runtime.h>
#include <math.h>

// Problem constants
#define BB 16
#define HH 16
#define NN 577
#define DD 64
#define CC 1024
#define MTOK (BB*NN)            // 9232
#define PLANE (BB*HH*NN*DD)     // 9,453,568 floats per q/k/v plane
#define OUT_ELEMS (MTOK*CC)     // 9,453,568
#define CTA_OFS OUT_ELEMS
#define CTL_OFS (OUT_ELEMS + MTOK)
#define QSCALE 0.125f           // 1/sqrt(64)
#define WQKV_ELEMS (3*CC*CC)    // 3,145,728
#define WPROJ_ELEMS (CC*CC)     // 1,048,576

// Scratch (device globals: allocation-free per harness rules)
__device__ float g_qkv[3u * PLANE];       // [3][B][H][N][D], q pre-scaled (fp32)
__device__ float g_attn[OUT_ELEMS];       // [B][N][C] attention output (tf32-rounded bits)
__device__ float g_x_r[OUT_ELEMS];        // x pre-rounded to tf32 bits
__device__ float g_wqkv_r[WQKV_ELEMS];    // w_qkv pre-rounded
__device__ float g_wproj_r[WPROJ_ELEMS];  // w_proj pre-rounded
__device__ float g_cls_logits[BB*HH*NN];  // per-head CLS-row logits (fp32)
__device__ float g_cls_max[BB*HH];
__device__ float g_cls_den[BB*HH];

__device__ __forceinline__ unsigned int f2tf32(float f) {
    unsigned int r;
    asm("cvt.rna.tf32.f32 %0, %1;" : "=r"(r) : "f"(f));
    return r;
}

#define MMA_TF32(d, a, b) \
    asm("mma.sync.aligned.m16n8k8.row.col.f32.tf32.tf32.f32 " \
        "{%0,%1,%2,%3}, {%4,%5,%6,%7}, {%8,%9}, {%0,%1,%2,%3};" \
        : "+f"((d)[0]), "+f"((d)[1]), "+f"((d)[2]), "+f"((d)[3]) \
        : "r"((a)[0]), "r"((a)[1]), "r"((a)[2]), "r"((a)[3]), \
          "r"((b)[0]), "r"((b)[1]))

#define CP_ASYNC16(smem_u32, gptr) \
    asm volatile("cp.async.cg.shared.global [%0], [%1], 16;" :: "r"(smem_u32), "l"(gptr) : "memory")
#define CP_COMMIT()  asm volatile("cp.async.commit_group;" ::: "memory")
#define CP_WAIT1()   asm volatile("cp.async.wait_group 1;" ::: "memory")
#define CP_WAIT0()   asm volatile("cp.async.wait_group 0;" ::: "memory")

// ---------------------------------------------------------------------------
// Pre-round inputs to tf32 bit patterns (one elementwise pass).
// ---------------------------------------------------------------------------
__global__ void round_inputs_kernel(const float* __restrict__ x,
                                    const float* __restrict__ wq,
                                    const float* __restrict__ wp)
{
    const int total = OUT_ELEMS + WQKV_ELEMS + WPROJ_ELEMS;
    for (int i = blockIdx.x * blockDim.x + threadIdx.x; i < total;
         i += gridDim.x * blockDim.x) {
        if (i < OUT_ELEMS) {
            g_x_r[i] = __uint_as_float(f2tf32(x[i]));
        } else if (i < OUT_ELEMS + WQKV_ELEMS) {
            int j = i - OUT_ELEMS;
            g_wqkv_r[j] = __uint_as_float(f2tf32(wq[j]));
        } else {
            int j = i - OUT_ELEMS - WQKV_ELEMS;
            g_wproj_r[j] = __uint_as_float(f2tf32(wp[j]));
        }
    }
}

// ---------------------------------------------------------------------------
// tf32 tensor-core GEMM, cp.async double-buffered (operands pre-rounded).
// C[m,n] = sum_k A[m,k] * W[n,k] (+bias). K = 1024.
// BM=BN=128, BK=32, 256 threads (8 warps as 4m x 2n, warp tile 32x64).
// mode 1: A=g_x_r, W=g_wqkv_r, epilogue scatters into g_qkv (q scaled)
// mode 2: A=g_attn (pre-rounded by flash), W=g_wproj_r, plain epilogue
// ---------------------------------------------------------------------------
#define GSTRIDE 36                      // words/row: bank = 4g+tg, conflict-free
#define TILE_WORDS (128 * GSTRIDE)      // 4608 words per operand tile
#define GEMM_SMEM (2 * 2 * TILE_WORDS * 4)   // 73728 B (2 stages x A+W)

__global__ __launch_bounds__(256) void mma_gemm_nt(
    const float* __restrict__ bias, float* __restrict__ Cout,
    int M, int N, int mode)
{
    extern __shared__ unsigned int sm[];
    const int K = 1024;
    const int NT = 32;   // K / 32 tiles

    const float* Abase = (mode == 2) ? g_attn : g_x_r;
    const float* Wbase = (mode == 2) ? g_wproj_r : g_wqkv_r;

    const int tid  = threadIdx.x;
    const int lane = tid & 31;
    const int warp = tid >> 5;
    const int wm   = warp & 3;
    const int wn   = warp >> 2;
    const int bm   = blockIdx.y * 128;
    const int bn   = blockIdx.x * 128;

    float acc[2][8][4];
    #pragma unroll
    for (int i = 0; i < 2; i++)
        #pragma unroll
        for (int j = 0; j < 8; j++)
            #pragma unroll
            for (int e = 0; e < 4; e++) acc[i][j][e] = 0.f;

    const int g  = lane >> 2;
    const int tg = lane & 3;

    // per-thread load coords: 4 float4 per operand (128 rows x 8 float4)
    int soff[4];
    const float* aptr[4];
    const float* wptr[4];
    #pragma unroll
    for (int i = 0; i < 4; i++) {
        int p   = i * 256 + tid;
        int row = p >> 3;
        int c4  = (p & 7) << 2;
        soff[i] = row * GSTRIDE + c4;
        int ar  = bm + row;
        aptr[i] = Abase + (size_t)((ar < M) ? ar : (M - 1)) * K + c4;  // clamp: rows>=M discarded
        wptr[i] = Wbase + (size_t)(bn + row) * K + c4;
    }

    const unsigned int sm_base = (unsigned int)__cvta_generic_to_shared(sm);

    // prologue: tile 0 -> stage 0
    {
        unsigned int as = sm_base;
        unsigned int ws = sm_base + TILE_WORDS * 4;
        #pragma unroll
        for (int i = 0; i < 4; i++) {
            CP_ASYNC16(as + soff[i] * 4, aptr[i]);
            CP_ASYNC16(ws + soff[i] * 4, wptr[i]);
        }
        CP_COMMIT();
    }

    for (int t = 0; t < NT; t++) {
        const int k0 = t * 32;
        // issue next tile into other stage (its buffer was released by the
        // trailing __syncthreads of iteration t-1)
        if (t + 1 < NT) {
            unsigned int as = sm_base + ((t + 1) & 1) * 2 * TILE_WORDS * 4;
            unsigned int ws = as + TILE_WORDS * 4;
            #pragma unroll
            for (int i = 0; i < 4; i++) {
                CP_ASYNC16(as + soff[i] * 4, aptr[i] + k0 + 32);
                CP_ASYNC16(ws + soff[i] * 4, wptr[i] + k0 + 32);
            }
            CP_COMMIT();
            CP_WAIT1();     // tile t complete, tile t+1 in flight
        } else {
            CP_WAIT0();
        }
        __syncthreads();

        const unsigned int* As = sm + (t & 1) * 2 * TILE_WORDS;
        const unsigned int* Ws = As + TILE_WORDS;

        #pragma unroll
        for (int ks = 0; ks < 4; ks++) {
            const int kb = ks << 3;
            unsigned int af[2][4], bf[8][2];
            #pragma unroll
            for (int mt = 0; mt < 2; mt++) {
                int r0 = wm * 32 + mt * 16 + g;
                af[mt][0] = As[r0 * GSTRIDE + kb + tg];
                af[mt][1] = As[(r0 + 8) * GSTRIDE + kb + tg];
                af[mt][2] = As[r0 * GSTRIDE + kb + tg + 4];
                af[mt][3] = As[(r0 + 8) * GSTRIDE + kb + tg + 4];
            }
            #pragma unroll
            for (int nt = 0; nt < 8; nt++) {
                int nr = wn * 64 + nt * 8 + g;
                bf[nt][0] = Ws[nr * GSTRIDE + kb + tg];
                bf[nt][1] = Ws[nr * GSTRIDE + kb + tg + 4];
            }
            #pragma unroll
            for (int mt = 0; mt < 2; mt++)
                #pragma unroll
                for (int nt = 0; nt < 8; nt++)
                    MMA_TF32(acc[mt][nt], af[mt], bf[nt]);
        }
        __syncthreads();   // stage (t&1) reads done before tile t+2 overwrites it
    }

    // Epilogue. c-elem e: row += (e>=2)*8, col = tg*2 + (e&1)
    #pragma unroll
    for (int mt = 0; mt < 2; mt++) {
        #pragma unroll
        for (int eh = 0; eh < 2; eh++) {
            int m = bm + wm * 32 + mt * 16 + g + eh * 8;
            if (m >= M) continue;
            if (mode == 1) {
                int b_  = m / NN;
                int tok = m - b_ * NN;
                #pragma unroll
                for (int nt = 0; nt < 8; nt++) {
                    #pragma unroll
                    for (int ec = 0; ec < 2; ec++) {
                        int n = bn + wn * 64 + nt * 8 + tg * 2 + ec;
                        float v = acc[mt][nt][eh * 2 + ec] + bias[n];
                        int which = n >> 10;
                        int rest  = n & 1023;
                        int h = rest >> 6;
                        int d = rest & 63;
                        if (which == 0) v *= QSCALE;
                        g_qkv[(size_t)which * PLANE + (((size_t)(b_ * HH + h) * NN + tok) << 6) + d] = v;
                    }
                }
            } else {
                #pragma unroll
                for (int nt = 0; nt < 8; nt++) {
                    int n = bn + wn * 64 + nt * 8 + tg * 2;
                    float2 v = make_float2(acc[mt][nt][eh * 2 + 0] + bias[n],
                                           acc[mt][nt][eh * 2 + 1] + bias[n + 1]);
                    *(float2*)(Cout + (size_t)m * N + n) = v;
                }
            }
        }
    }
}

// ---------------------------------------------------------------------------
// Tensor-core flash attention (tf32 mma) — R6 structure (no reg prefetch).
// Grid (5 q-tiles of 128, 256 bh), 256 threads = 8 warps x 16 q-rows.
// Epilogue writes g_attn pre-rounded to tf32 bits (consumed only by mode-2
// GEMM, which previously applied the same rounding at load — bit-identical).
// ---------------------------------------------------------------------------
#define FA_SROW 68
#define FA_BQ   128
#define FA_SMEM ((FA_BQ*FA_SROW + 64*FA_SROW + 64*FA_SROW + FA_BQ*FA_SROW) * 4)

__global__ __launch_bounds__(256) void flash_mma_kernel()
{
    extern __shared__ unsigned int smu[];
    unsigned int* Qs = smu;                      // [128][68] tf32
    unsigned int* Ks = Qs + FA_BQ * FA_SROW;     // [64][68]  tf32
    unsigned int* Vs = Ks + 64 * FA_SROW;        // [64][68]  tf32
    unsigned int* Ps = Vs + 64 * FA_SROW;        // [128][68] tf32

    const int tid  = threadIdx.x;
    const int lane = tid & 31;
    const int warp = tid >> 5;
    const int g    = lane >> 2;
    const int tg   = lane & 3;
    const int qt   = blockIdx.x;          // 0..4
    const int bh   = blockIdx.y;          // 0..255
    const int q0g  = qt * FA_BQ;
    const int wr   = warp * 16;

    const float* Qg = g_qkv + (size_t)bh * NN * DD;
    const float* Kg = g_qkv + (size_t)PLANE + (size_t)bh * NN * DD;
    const float* Vg = g_qkv + 2u * (size_t)PLANE + (size_t)bh * NN * DD;

    // Load Q tile (tf32). 128 rows x 16 float4 = 2048, 8 per thread.
    #pragma unroll
    for (int i = 0; i < 8; i++) {
        int p   = i * 256 + tid;
        int row = p >> 4;
        int c4  = (p & 15) << 2;
        int tok = q0g + row; if (tok > NN - 1) tok = NN - 1;   // clamp (rows >= NN unused)
        float4 v = *(const float4*)(Qg + (size_t)tok * DD + c4);
        *(uint4*)(Qs + row * FA_SROW + c4) =
            make_uint4(f2tf32(v.x), f2tf32(v.y), f2tf32(v.z), f2tf32(v.w));
    }

    float oacc[8][4];
    #pragma unroll
    for (int nt = 0; nt < 8; nt++)
        #pragma unroll
        for (int e = 0; e < 4; e++) oacc[nt][e] = 0.f;
    float m_i[2] = { -1e30f, -1e30f };
    float l_i[2] = { 0.f, 0.f };

    for (int kt = 0; kt < 10; kt++) {
        const int k0g = kt * 64;
        __syncthreads();   // prior-iteration Ks/Vs reads complete (also covers Q store)

        // Load K/V tiles (tf32). 64 rows x 16 float4 each, 4+4 per thread.
        #pragma unroll
        for (int i = 0; i < 4; i++) {
            int p   = i * 256 + tid;
            int row = p >> 4;
            int c4  = (p & 15) << 2;
            int tok = k0g + row; if (tok > NN - 1) tok = NN - 1;  // clamp (masked later)
            float4 kv = *(const float4*)(Kg + (size_t)tok * DD + c4);
            float4 vv = *(const float4*)(Vg + (size_t)tok * DD + c4);
            *(uint4*)(Ks + row * FA_SROW + c4) =
                make_uint4(f2tf32(kv.x), f2tf32(kv.y), f2tf32(kv.z), f2tf32(kv.w));
            *(uint4*)(Vs + row * FA_SROW + c4) =
                make_uint4(f2tf32(vv.x), f2tf32(vv.y), f2tf32(vv.z), f2tf32(vv.w));
        }
        __syncthreads();

        // ---- S = Q K^T ----
        float sacc[8][4];
        #pragma unroll
        for (int nt = 0; nt < 8; nt++)
            #pragma unroll
            for (int e = 0; e < 4; e++) sacc[nt][e] = 0.f;

        #pragma unroll
        for (int ks = 0; ks < 8; ks++) {
            const int kb = ks << 3;
            unsigned int af[4], bf[8][2];
            af[0] = Qs[(wr + g) * FA_SROW + kb + tg];
            af[1] = Qs[(wr + g + 8) * FA_SROW + kb + tg];
            af[2] = Qs[(wr + g) * FA_SROW + kb + tg + 4];
            af[3] = Qs[(wr + g + 8) * FA_SROW + kb + tg + 4];
            #pragma unroll
            for (int nt = 0; nt < 8; nt++) {
                bf[nt][0] = Ks[(nt * 8 + g) * FA_SROW + kb + tg];
                bf[nt][1] = Ks[(nt * 8 + g) * FA_SROW + kb + tg + 4];
            }
            #pragma unroll
            for (int nt = 0; nt < 8; nt++)
                MMA_TF32(sacc[nt], af, bf[nt]);
        }

        // ---- online softmax on fragments ----
        #pragma unroll
        for (int eh = 0; eh < 2; eh++) {
            float mloc = -1e30f;
            #pragma unroll
            for (int nt = 0; nt < 8; nt++) {
                #pragma unroll
                for (int ec = 0; ec < 2; ec++) {
                    int key = k0g + nt * 8 + tg * 2 + ec;
                    if (key >= NN) sacc[nt][eh * 2 + ec] = -1e30f;
                    mloc = fmaxf(mloc, sacc[nt][eh * 2 + ec]);
                }
            }
            mloc = fmaxf(mloc, __shfl_xor_sync(0xffffffffu, mloc, 1));
            mloc = fmaxf(mloc, __shfl_xor_sync(0xffffffffu, mloc, 2));
            float m_new = fmaxf(m_i[eh], mloc);
            float alpha = __expf(m_i[eh] - m_new);

            float psum = 0.f;
            int prow = (wr + g + eh * 8) * FA_SROW;
            #pragma unroll
            for (int nt = 0; nt < 8; nt++) {
                float p0 = __expf(sacc[nt][eh * 2 + 0] - m_new);
                float p1 = __expf(sacc[nt][eh * 2 + 1] - m_new);
                psum += p0 + p1;
                *(uint2*)(Ps + prow + nt * 8 + tg * 2) = make_uint2(f2tf32(p0), f2tf32(p1));
            }
            psum += __shfl_xor_sync(0xffffffffu, psum, 1);
            psum += __shfl_xor_sync(0xffffffffu, psum, 2);
            l_i[eh] = l_i[eh] * alpha + psum;
            m_i[eh] = m_new;
            #pragma unroll
            for (int nt = 0; nt < 8; nt++) {
                oacc[nt][eh * 2 + 0] *= alpha;
                oacc[nt][eh * 2 + 1] *= alpha;
            }
        }
        __syncwarp();   // Ps strip visible within warp

        // ---- O += P V ----
        #pragma unroll
        for (int ks = 0; ks < 8; ks++) {
            const int kb = ks << 3;
            unsigned int af[4], bf[8][2];
            af[0] = Ps[(wr + g) * FA_SROW + kb + tg];
            af[1] = Ps[(wr + g + 8) * FA_SROW + kb + tg];
            af[2] = Ps[(wr + g) * FA_SROW + kb + tg + 4];
            af[3] = Ps[(wr + g + 8) * FA_SROW + kb + tg + 4];
            #pragma unroll
            for (int nt = 0; nt < 8; nt++) {
                bf[nt][0] = Vs[(kb + tg) * FA_SROW + nt * 8 + g];
                bf[nt][1] = Vs[(kb + tg + 4) * FA_SROW + nt * 8 + g];
            }
            #pragma unroll
            for (int nt = 0; nt < 8; nt++)
                MMA_TF32(oacc[nt], af, bf[nt]);
        }
        __syncwarp();   // Ps reads done before next-iter overwrite
    }

    // ---- write O (pre-rounded to tf32 bits for the mode-2 GEMM) ----
    const int b_ = bh >> 4, h = bh & 15;
    #pragma unroll
    for (int eh = 0; eh < 2; eh++) {
        int tok = q0g + wr + g + eh * 8;
        if (tok >= NN) continue;
        float inv = 1.f / l_i[eh];
        float* o = g_attn + ((size_t)b_ * NN + tok) * CC + h * DD;
        #pragma unroll
        for (int nt = 0; nt < 8; nt++) {
            uint2 v = make_uint2(f2tf32(oacc[nt][eh * 2 + 0] * inv),
                                 f2tf32(oacc[nt][eh * 2 + 1] * inv));
            *(uint2*)(o + nt * 8 + tg * 2) = v;
        }
    }
}

// ---------------------------------------------------------------------------
// CLS-row logits per (b,h): logits[m] = q0 . k[m]; also max & softmax denom
// ---------------------------------------------------------------------------
__global__ __launch_bounds__(128) void cls_logits_kernel()
{
    __shared__ float q0s[64];
    __shared__ float red[128];
    const int bh  = blockIdx.x;
    const int tid = threadIdx.x;
    const float* Qg = g_qkv + (size_t)bh * NN * DD;            // q already scaled
    const float* Kg = g_qkv + (size_t)PLANE + (size_t)bh * NN * DD;

    if (tid < 64) q0s[tid] = Qg[tid];
    __syncthreads();

    float lg[5];
    float mloc = -1e30f;
    #pragma unroll
    for (int i = 0; i < 5; i++) {
        int m = tid + i*128;
        float s = -1e30f;
        if (m < NN) {
            s = 0.f;
            const float* kr = Kg + (size_t)m * DD;
            #pragma unroll
            for (int d4 = 0; d4 < 64; d4 += 4) {
                float4 k4 = *(const float4*)(kr + d4);
                s += q0s[d4]*k4.x + q0s[d4+1]*k4.y + q0s[d4+2]*k4.z + q0s[d4+3]*k4.w;
            }
            g_cls_logits[(size_t)bh * NN + m] = s;
        }
        lg[i] = s;
        mloc = fmaxf(mloc, s);
    }

    red[tid] = mloc; __syncthreads();
    for (int o = 64; o > 0; o >>= 1) {
        if (tid < o) red[tid] = fmaxf(red[tid], red[tid+o]);
        __syncthreads();
    }
    float mx = red[0];
    __syncthreads();

    float se = 0.f;
    #pragma unroll
    for (int i = 0; i < 5; i++)
        if (lg[i] > -1e29f) se += __expf(lg[i] - mx);
    red[tid] = se; __syncthreads();
    for (int o = 64; o > 0; o >>= 1) {
        if (tid < o) red[tid] += red[tid+o];
        __syncthreads();
    }
    if (tid == 0) { g_cls_max[bh] = mx; g_cls_den[bh] = red[0]; }
}

// Head-mean of CLS logits and CLS attention
__global__ void cls_out_kernel(float* __restrict__ out_cta, float* __restrict__ out_ctl)
{
    int idx = blockIdx.x * blockDim.x + threadIdx.x;
    if (idx >= MTOK) return;
    int b_ = idx / NN;
    int m  = idx - b_ * NN;
    float sl = 0.f, sa = 0.f;
    #pragma unroll
    for (int h = 0; h < HH; h++) {
        int bh = b_ * HH + h;
        float l = g_cls_logits[(size_t)bh * NN + m];
        sl += l;
        sa += __expf(l - g_cls_max[bh]) / g_cls_den[bh];
    }
    out_ctl[idx] = sl * (1.f / 16.f);
    out_cta[idx] = sa * (1.f / 16.f);
}

// ---------------------------------------------------------------------------
extern "C" void kernel_launch(void* const* d_in, const int* in_sizes, int n_in,
                              void* d_out, int out_size)
{
    const float* x      = (const float*)d_in[0];
    const float* w_qkv  = (const float*)d_in[1];
    const float* b_qkv  = (const float*)d_in[2];
    const float* w_proj = (const float*)d_in[3];
    const float* b_proj = (const float*)d_in[4];
    float* out = (float*)d_out;

    cudaFuncSetAttribute(mma_gemm_nt,
                         cudaFuncAttributeMaxDynamicSharedMemorySize, GEMM_SMEM);
    cudaFuncSetAttribute(flash_mma_kernel,
                         cudaFuncAttributeMaxDynamicSharedMemorySize, FA_SMEM);

    // 0) Pre-round x / w_qkv / w_proj to tf32 bits
    round_inputs_kernel<<<592, 256>>>(x, w_qkv, w_proj);

    // 1) QKV projection + scatter (q scaled) — cp.async tf32 GEMM
    {
        dim3 grid(3*CC/128, (MTOK + 127) / 128);
        mma_gemm_nt<<<grid, 256, GEMM_SMEM>>>(b_qkv, nullptr, MTOK, 3*CC, 1);
    }

    // 2) Flash attention — tf32 tensor cores
    {
        dim3 grid((NN + FA_BQ - 1) / FA_BQ, BB*HH);   // (5, 256)
        flash_mma_kernel<<<grid, 256, FA_SMEM>>>();
    }

    // 3) CLS-row outputs (full fp32)
    cls_logits_kernel<<<BB*HH, 128>>>();
    cls_out_kernel<<<(MTOK + 255) / 256, 256>>>(out + CTA_OFS, out + CTL_OFS);

    // 4) Output projection — cp.async tf32 GEMM
    {
        dim3 grid(CC/128, (MTOK + 127) / 128);
        mma_gemm_nt<<<grid, 256, GEMM_SMEM>>>(b_proj, out, MTOK, CC, 2);
    }
}

// round 11
// speedup vs baseline: 1.2037x; 1.0543x over previous
#include <cuda_runtime.h>
#include <math.h>

// Problem constants
#define BB 16
#define HH 16
#define NN 577
#define DD 64
#define CC 1024
#define MTOK (BB*NN)            // 9232
#define PLANE (BB*HH*NN*DD)     // 9,453,568 floats per q/k/v plane
#define OUT_ELEMS (MTOK*CC)     // 9,453,568
#define CTA_OFS OUT_ELEMS
#define CTL_OFS (OUT_ELEMS + MTOK)
#define QSCALE 0.125f           // 1/sqrt(64)
#define WQKV_ELEMS (3*CC*CC)    // 3,145,728
#define WPROJ_ELEMS (CC*CC)     // 1,048,576

// Scratch (device globals: allocation-free per harness rules)
__device__ float g_qkv[3u * PLANE];       // [3][B][H][N][D], q pre-scaled (fp32)
__device__ float g_attn[OUT_ELEMS];       // [B][N][C] attention output (tf32-rounded bits)
__device__ float g_x_r[OUT_ELEMS];        // x pre-rounded to tf32 bits
__device__ float g_wqkv_r[WQKV_ELEMS];    // w_qkv pre-rounded
__device__ float g_wproj_r[WPROJ_ELEMS];  // w_proj pre-rounded
__device__ float g_cls_logits[BB*HH*NN];  // per-head CLS-row logits (fp32)
__device__ float g_cls_max[BB*HH];
__device__ float g_cls_den[BB*HH];

__device__ __forceinline__ unsigned int f2tf32(float f) {
    unsigned int r;
    asm("cvt.rna.tf32.f32 %0, %1;" : "=r"(r) : "f"(f));
    return r;
}

#define MMA_TF32(d, a, b) \
    asm("mma.sync.aligned.m16n8k8.row.col.f32.tf32.tf32.f32 " \
        "{%0,%1,%2,%3}, {%4,%5,%6,%7}, {%8,%9}, {%0,%1,%2,%3};" \
        : "+f"((d)[0]), "+f"((d)[1]), "+f"((d)[2]), "+f"((d)[3]) \
        : "r"((a)[0]), "r"((a)[1]), "r"((a)[2]), "r"((a)[3]), \
          "r"((b)[0]), "r"((b)[1]))

#define LDSM_X4(r0, r1, r2, r3, addr) \
    asm volatile("ldmatrix.sync.aligned.m8n8.x4.shared.b16 {%0,%1,%2,%3}, [%4];" \
        : "=r"(r0), "=r"(r1), "=r"(r2), "=r"(r3) : "r"(addr))

#define CP_ASYNC16(smem_u32, gptr) \
    asm volatile("cp.async.cg.shared.global [%0], [%1], 16;" :: "r"(smem_u32), "l"(gptr) : "memory")
#define CP_COMMIT()  asm volatile("cp.async.commit_group;" ::: "memory")
#define CP_WAIT1()   asm volatile("cp.async.wait_group 1;" ::: "memory")
#define CP_WAIT0()   asm volatile("cp.async.wait_group 0;" ::: "memory")

// ---------------------------------------------------------------------------
// Pre-round inputs to tf32 bit patterns (one elementwise pass).
// ---------------------------------------------------------------------------
__global__ void round_inputs_kernel(const float* __restrict__ x,
                                    const float* __restrict__ wq,
                                    const float* __restrict__ wp)
{
    const int total = OUT_ELEMS + WQKV_ELEMS + WPROJ_ELEMS;
    for (int i = blockIdx.x * blockDim.x + threadIdx.x; i < total;
         i += gridDim.x * blockDim.x) {
        if (i < OUT_ELEMS) {
            g_x_r[i] = __uint_as_float(f2tf32(x[i]));
        } else if (i < OUT_ELEMS + WQKV_ELEMS) {
            int j = i - OUT_ELEMS;
            g_wqkv_r[j] = __uint_as_float(f2tf32(wq[j]));
        } else {
            int j = i - OUT_ELEMS - WQKV_ELEMS;
            g_wproj_r[j] = __uint_as_float(f2tf32(wp[j]));
        }
    }
}

// ---------------------------------------------------------------------------
// tf32 tensor-core GEMM, cp.async double-buffered, ldmatrix fragment loads.
// C[m,n] = sum_k A[m,k] * W[n,k] (+bias). K = 1024.
// BM=BN=128, BK=32, 256 threads (8 warps as 4m x 2n, warp tile 32x64).
// mode 1: A=g_x_r, W=g_wqkv_r, epilogue scatters into g_qkv (q scaled)
// mode 2: A=g_attn (pre-rounded by flash), W=g_wproj_r, plain epilogue
// ---------------------------------------------------------------------------
#define GSTRIDE 36                      // words/row: LDSM rows tile all 32 banks
#define TILE_WORDS (128 * GSTRIDE)
#define GEMM_SMEM (2 * 2 * TILE_WORDS * 4)   // 73728 B (2 stages x A+W)

__global__ __launch_bounds__(256) void mma_gemm_nt(
    const float* __restrict__ bias, float* __restrict__ Cout,
    int M, int N, int mode)
{
    extern __shared__ unsigned int sm[];
    const int K = 1024;
    const int NT = 32;

    const float* Abase = (mode == 2) ? g_attn : g_x_r;
    const float* Wbase = (mode == 2) ? g_wproj_r : g_wqkv_r;

    const int tid  = threadIdx.x;
    const int lane = tid & 31;
    const int warp = tid >> 5;
    const int wm   = warp & 3;
    const int wn   = warp >> 2;
    const int bm   = blockIdx.y * 128;
    const int bn   = blockIdx.x * 128;

    float acc[2][8][4];
    #pragma unroll
    for (int i = 0; i < 2; i++)
        #pragma unroll
        for (int j = 0; j < 8; j++)
            #pragma unroll
            for (int e = 0; e < 4; e++) acc[i][j][e] = 0.f;

    const int g  = lane >> 2;
    const int tg = lane & 3;

    // cp.async load coords: 4 float4 per operand (128 rows x 8 float4)
    int soff[4];
    const float* aptr[4];
    const float* wptr[4];
    #pragma unroll
    for (int i = 0; i < 4; i++) {
        int p   = i * 256 + tid;
        int row = p >> 3;
        int c4  = (p & 7) << 2;
        soff[i] = row * GSTRIDE + c4;
        int ar  = bm + row;
        aptr[i] = Abase + (size_t)((ar < M) ? ar : (M - 1)) * K + c4;  // clamp: rows>=M discarded
        wptr[i] = Wbase + (size_t)(bn + row) * K + c4;
    }

    const unsigned int sm_base = (unsigned int)__cvta_generic_to_shared(sm);

    // ldmatrix per-lane word offsets (within a tile)
    // A: matrices {rows 0-7,k0-3},{rows 8-15,k0-3},{rows 0-7,k4-7},{rows 8-15,k4-7}
    const int a_lrow = lane & 15;
    const int a_lcol = (lane >> 4) << 2;
    const int a_off0 = (wm * 32 + 0  + a_lrow) * GSTRIDE + a_lcol;
    const int a_off1 = (wm * 32 + 16 + a_lrow) * GSTRIDE + a_lcol;
    // B: LDSM p covers nt=2p,2p+1: lanes 0-15 -> nt=2p rows (+k half), 16-31 -> nt=2p+1
    const int b_lrow = ((lane >> 4) << 3) + (lane & 7);
    const int b_lcol = ((lane >> 3) & 1) << 2;
    const int b_off  = (wn * 64 + b_lrow) * GSTRIDE + b_lcol;   // + p*16*GSTRIDE + kb

    // prologue: tile 0 -> stage 0
    {
        unsigned int as = sm_base;
        unsigned int ws = sm_base + TILE_WORDS * 4;
        #pragma unroll
        for (int i = 0; i < 4; i++) {
            CP_ASYNC16(as + soff[i] * 4, aptr[i]);
            CP_ASYNC16(ws + soff[i] * 4, wptr[i]);
        }
        CP_COMMIT();
    }

    for (int t = 0; t < NT; t++) {
        const int k0 = t * 32;
        if (t + 1 < NT) {
            unsigned int as = sm_base + ((t + 1) & 1) * 2 * TILE_WORDS * 4;
            unsigned int ws = as + TILE_WORDS * 4;
            #pragma unroll
            for (int i = 0; i < 4; i++) {
                CP_ASYNC16(as + soff[i] * 4, aptr[i] + k0 + 32);
                CP_ASYNC16(ws + soff[i] * 4, wptr[i] + k0 + 32);
            }
            CP_COMMIT();
            CP_WAIT1();
        } else {
            CP_WAIT0();
        }
        __syncthreads();

        const unsigned int as_u32 = sm_base + (t & 1) * 2 * TILE_WORDS * 4;
        const unsigned int ws_u32 = as_u32 + TILE_WORDS * 4;

        #pragma unroll
        for (int ks = 0; ks < 4; ks++) {
            const int kb = ks << 3;
            unsigned int af[2][4], bf[8][2];
            LDSM_X4(af[0][0], af[0][1], af[0][2], af[0][3], as_u32 + (a_off0 + kb) * 4);
            LDSM_X4(af[1][0], af[1][1], af[1][2], af[1][3], as_u32 + (a_off1 + kb) * 4);
            #pragma unroll
            for (int p = 0; p < 4; p++) {
                LDSM_X4(bf[2*p][0], bf[2*p][1], bf[2*p+1][0], bf[2*p+1][1],
                        ws_u32 + (b_off + p * 16 * GSTRIDE + kb) * 4);
            }
            #pragma unroll
            for (int mt = 0; mt < 2; mt++)
                #pragma unroll
                for (int nt = 0; nt < 8; nt++)
                    MMA_TF32(acc[mt][nt], af[mt], bf[nt]);
        }
        __syncthreads();   // stage reads done before tile t+2 overwrites it
    }

    // Epilogue. c-elem e: row += (e>=2)*8, col = tg*2 + (e&1)
    #pragma unroll
    for (int mt = 0; mt < 2; mt++) {
        #pragma unroll
        for (int eh = 0; eh < 2; eh++) {
            int m = bm + wm * 32 + mt * 16 + g + eh * 8;
            if (m >= M) continue;
            if (mode == 1) {
                int b_  = m / NN;
                int tok = m - b_ * NN;
                #pragma unroll
                for (int nt = 0; nt < 8; nt++) {
                    #pragma unroll
                    for (int ec = 0; ec < 2; ec++) {
                        int n = bn + wn * 64 + nt * 8 + tg * 2 + ec;
                        float v = acc[mt][nt][eh * 2 + ec] + bias[n];
                        int which = n >> 10;
                        int rest  = n & 1023;
                        int h = rest >> 6;
                        int d = rest & 63;
                        if (which == 0) v *= QSCALE;
                        g_qkv[(size_t)which * PLANE + (((size_t)(b_ * HH + h) * NN + tok) << 6) + d] = v;
                    }
                }
            } else {
                #pragma unroll
                for (int nt = 0; nt < 8; nt++) {
                    int n = bn + wn * 64 + nt * 8 + tg * 2;
                    float2 v = make_float2(acc[mt][nt][eh * 2 + 0] + bias[n],
                                           acc[mt][nt][eh * 2 + 1] + bias[n + 1]);
                    *(float2*)(Cout + (size_t)m * N + n) = v;
                }
            }
        }
    }
}

// ---------------------------------------------------------------------------
// Tensor-core flash attention (tf32 mma), ldmatrix for Q/K/P fragments.
// Grid (5 q-tiles of 128, 256 bh), 256 threads = 8 warps x 16 q-rows.
// Epilogue writes g_attn pre-rounded to tf32 bits.
// ---------------------------------------------------------------------------
#define FA_SROW 68
#define FA_BQ   128
#define KS_OFF  (FA_BQ * FA_SROW)
#define VS_OFF  (KS_OFF + 64 * FA_SROW)
#define PS_OFF  (VS_OFF + 64 * FA_SROW)
#define FA_SMEM ((PS_OFF + FA_BQ * FA_SROW) * 4)

__global__ __launch_bounds__(256) void flash_mma_kernel()
{
    extern __shared__ unsigned int smu[];
    unsigned int* Qs = smu;                      // [128][68] tf32
    unsigned int* Ks = smu + KS_OFF;             // [64][68]  tf32
    unsigned int* Vs = smu + VS_OFF;             // [64][68]  tf32
    unsigned int* Ps = smu + PS_OFF;             // [128][68] tf32

    const int tid  = threadIdx.x;
    const int lane = tid & 31;
    const int warp = tid >> 5;
    const int g    = lane >> 2;
    const int tg   = lane & 3;
    const int qt   = blockIdx.x;          // 0..4
    const int bh   = blockIdx.y;          // 0..255
    const int q0g  = qt * FA_BQ;
    const int wr   = warp * 16;

    const float* Qg = g_qkv + (size_t)bh * NN * DD;
    const float* Kg = g_qkv + (size_t)PLANE + (size_t)bh * NN * DD;
    const float* Vg = g_qkv + 2u * (size_t)PLANE + (size_t)bh * NN * DD;

    // Load Q tile (tf32). 128 rows x 16 float4 = 2048, 8 per thread.
    #pragma unroll
    for (int i = 0; i < 8; i++) {
        int p   = i * 256 + tid;
        int row = p >> 4;
        int c4  = (p & 15) << 2;
        int tok = q0g + row; if (tok > NN - 1) tok = NN - 1;   // clamp (rows >= NN unused)
        float4 v = *(const float4*)(Qg + (size_t)tok * DD + c4);
        *(uint4*)(Qs + row * FA_SROW + c4) =
            make_uint4(f2tf32(v.x), f2tf32(v.y), f2tf32(v.z), f2tf32(v.w));
    }

    const unsigned int smu_base = (unsigned int)__cvta_generic_to_shared(smu);
    const int a_lrow = lane & 15;
    const int a_lcol = (lane >> 4) << 2;
    const unsigned int q_addr = smu_base + (((wr + a_lrow) * FA_SROW) + a_lcol) * 4;
    const unsigned int p_addr = smu_base + ((PS_OFF + (wr + a_lrow) * FA_SROW) + a_lcol) * 4;
    const int b_lrow = ((lane >> 4) << 3) + (lane & 7);
    const int b_lcol = ((lane >> 3) & 1) << 2;
    const unsigned int k_addr = smu_base + ((KS_OFF + b_lrow * FA_SROW) + b_lcol) * 4;

    float oacc[8][4];
    #pragma unroll
    for (int nt = 0; nt < 8; nt++)
        #pragma unroll
        for (int e = 0; e < 4; e++) oacc[nt][e] = 0.f;
    float m_i[2] = { -1e30f, -1e30f };
    float l_i[2] = { 0.f, 0.f };

    for (int kt = 0; kt < 10; kt++) {
        const int k0g = kt * 64;
        __syncthreads();   // prior-iteration Ks/Vs reads complete (also covers Q store)

        // Load K/V tiles (tf32). 64 rows x 16 float4 each, 4+4 per thread.
        #pragma unroll
        for (int i = 0; i < 4; i++) {
            int p   = i * 256 + tid;
            int row = p >> 4;
            int c4  = (p & 15) << 2;
            int tok = k0g + row; if (tok > NN - 1) tok = NN - 1;  // clamp (masked later)
            float4 kv = *(const float4*)(Kg + (size_t)tok * DD + c4);
            float4 vv = *(const float4*)(Vg + (size_t)tok * DD + c4);
            *(uint4*)(Ks + row * FA_SROW + c4) =
                make_uint4(f2tf32(kv.x), f2tf32(kv.y), f2tf32(kv.z), f2tf32(kv.w));
            *(uint4*)(Vs + row * FA_SROW + c4) =
                make_uint4(f2tf32(vv.x), f2tf32(vv.y), f2tf32(vv.z), f2tf32(vv.w));
        }
        __syncthreads();

        // ---- S = Q K^T ----
        float sacc[8][4];
        #pragma unroll
        for (int nt = 0; nt < 8; nt++)
            #pragma unroll
            for (int e = 0; e < 4; e++) sacc[nt][e] = 0.f;

        #pragma unroll
        for (int ks = 0; ks < 8; ks++) {
            const int kb = ks << 3;
            unsigned int af[4], bf[8][2];
            LDSM_X4(af[0], af[1], af[2], af[3], q_addr + kb * 4);
            #pragma unroll
            for (int p = 0; p < 4; p++) {
                LDSM_X4(bf[2*p][0], bf[2*p][1], bf[2*p+1][0], bf[2*p+1][1],
                        k_addr + (p * 16 * FA_SROW + kb) * 4);
            }
            #pragma unroll
            for (int nt = 0; nt < 8; nt++)
                MMA_TF32(sacc[nt], af, bf[nt]);
        }

        // ---- online softmax on fragments ----
        #pragma unroll
        for (int eh = 0; eh < 2; eh++) {
            float mloc = -1e30f;
            #pragma unroll
            for (int nt = 0; nt < 8; nt++) {
                #pragma unroll
                for (int ec = 0; ec < 2; ec++) {
                    int key = k0g + nt * 8 + tg * 2 + ec;
                    if (key >= NN) sacc[nt][eh * 2 + ec] = -1e30f;
                    mloc = fmaxf(mloc, sacc[nt][eh * 2 + ec]);
                }
            }
            mloc = fmaxf(mloc, __shfl_xor_sync(0xffffffffu, mloc, 1));
            mloc = fmaxf(mloc, __shfl_xor_sync(0xffffffffu, mloc, 2));
            float m_new = fmaxf(m_i[eh], mloc);
            float alpha = __expf(m_i[eh] - m_new);

            float psum = 0.f;
            int prow = (wr + g + eh * 8) * FA_SROW;
            #pragma unroll
            for (int nt = 0; nt < 8; nt++) {
                float p0 = __expf(sacc[nt][eh * 2 + 0] - m_new);
                float p1 = __expf(sacc[nt][eh * 2 + 1] - m_new);
                psum += p0 + p1;
                *(uint2*)(Ps + prow + nt * 8 + tg * 2) = make_uint2(f2tf32(p0), f2tf32(p1));
            }
            psum += __shfl_xor_sync(0xffffffffu, psum, 1);
            psum += __shfl_xor_sync(0xffffffffu, psum, 2);
            l_i[eh] = l_i[eh] * alpha + psum;
            m_i[eh] = m_new;
            #pragma unroll
            for (int nt = 0; nt < 8; nt++) {
                oacc[nt][eh * 2 + 0] *= alpha;
                oacc[nt][eh * 2 + 1] *= alpha;
            }
        }
        __syncwarp();   // Ps strip visible within warp

        // ---- O += P V : A = P (LDSM), B = Vs (scalar, transposed access) ----
        #pragma unroll
        for (int ks = 0; ks < 8; ks++) {
            const int kb = ks << 3;
            unsigned int af[4], bf[8][2];
            LDSM_X4(af[0], af[1], af[2], af[3], p_addr + kb * 4);
            #pragma unroll
            for (int nt = 0; nt < 8; nt++) {
                bf[nt][0] = Vs[(kb + tg) * FA_SROW + nt * 8 + g];
                bf[nt][1] = Vs[(kb + tg + 4) * FA_SROW + nt * 8 + g];
            }
            #pragma unroll
            for (int nt = 0; nt < 8; nt++)
                MMA_TF32(oacc[nt], af, bf[nt]);
        }
        __syncwarp();   // Ps reads done before next-iter overwrite
    }

    // ---- write O (pre-rounded to tf32 bits for the mode-2 GEMM) ----
    const int b_ = bh >> 4, h = bh & 15;
    #pragma unroll
    for (int eh = 0; eh < 2; eh++) {
        int tok = q0g + wr + g + eh * 8;
        if (tok >= NN) continue;
        float inv = 1.f / l_i[eh];
        float* o = g_attn + ((size_t)b_ * NN + tok) * CC + h * DD;
        #pragma unroll
        for (int nt = 0; nt < 8; nt++) {
            uint2 v = make_uint2(f2tf32(oacc[nt][eh * 2 + 0] * inv),
                                 f2tf32(oacc[nt][eh * 2 + 1] * inv));
            *(uint2*)(o + nt * 8 + tg * 2) = v;
        }
    }
}

// ---------------------------------------------------------------------------
// CLS-row logits per (b,h): logits[m] = q0 . k[m]; also max & softmax denom
// ---------------------------------------------------------------------------
__global__ __launch_bounds__(128) void cls_logits_kernel()
{
    __shared__ float q0s[64];
    __shared__ float red[128];
    const int bh  = blockIdx.x;
    const int tid = threadIdx.x;
    const float* Qg = g_qkv + (size_t)bh * NN * DD;            // q already scaled
    const float* Kg = g_qkv + (size_t)PLANE + (size_t)bh * NN * DD;

    if (tid < 64) q0s[tid] = Qg[tid];
    __syncthreads();

    float lg[5];
    float mloc = -1e30f;
    #pragma unroll
    for (int i = 0; i < 5; i++) {
        int m = tid + i*128;
        float s = -1e30f;
        if (m < NN) {
            s = 0.f;
            const float* kr = Kg + (size_t)m * DD;
            #pragma unroll
            for (int d4 = 0; d4 < 64; d4 += 4) {
                float4 k4 = *(const float4*)(kr + d4);
                s += q0s[d4]*k4.x + q0s[d4+1]*k4.y + q0s[d4+2]*k4.z + q0s[d4+3]*k4.w;
            }
            g_cls_logits[(size_t)bh * NN + m] = s;
        }
        lg[i] = s;
        mloc = fmaxf(mloc, s);
    }

    red[tid] = mloc; __syncthreads();
    for (int o = 64; o > 0; o >>= 1) {
        if (tid < o) red[tid] = fmaxf(red[tid], red[tid+o]);
        __syncthreads();
    }
    float mx = red[0];
    __syncthreads();

    float se = 0.f;
    #pragma unroll
    for (int i = 0; i < 5; i++)
        if (lg[i] > -1e29f) se += __expf(lg[i] - mx);
    red[tid] = se; __syncthreads();
    for (int o = 64; o > 0; o >>= 1) {
        if (tid < o) red[tid] += red[tid+o];
        __syncthreads();
    }
    if (tid == 0) { g_cls_max[bh] = mx; g_cls_den[bh] = red[0]; }
}

// Head-mean of CLS logits and CLS attention
__global__ void cls_out_kernel(float* __restrict__ out_cta, float* __restrict__ out_ctl)
{
    int idx = blockIdx.x * blockDim.x + threadIdx.x;
    if (idx >= MTOK) return;
    int b_ = idx / NN;
    int m  = idx - b_ * NN;
    float sl = 0.f, sa = 0.f;
    #pragma unroll
    for (int h = 0; h < HH; h++) {
        int bh = b_ * HH + h;
        float l = g_cls_logits[(size_t)bh * NN + m];
        sl += l;
        sa += __expf(l - g_cls_max[bh]) / g_cls_den[bh];
    }
    out_ctl[idx] = sl * (1.f / 16.f);
    out_cta[idx] = sa * (1.f / 16.f);
}

// ---------------------------------------------------------------------------
extern "C" void kernel_launch(void* const* d_in, const int* in_sizes, int n_in,
                              void* d_out, int out_size)
{
    const float* x      = (const float*)d_in[0];
    const float* w_qkv  = (const float*)d_in[1];
    const float* b_qkv  = (const float*)d_in[2];
    const float* w_proj = (const float*)d_in[3];
    const float* b_proj = (const float*)d_in[4];
    float* out = (float*)d_out;

    cudaFuncSetAttribute(mma_gemm_nt,
                         cudaFuncAttributeMaxDynamicSharedMemorySize, GEMM_SMEM);
    cudaFuncSetAttribute(flash_mma_kernel,
                         cudaFuncAttributeMaxDynamicSharedMemorySize, FA_SMEM);

    // 0) Pre-round x / w_qkv / w_proj to tf32 bits
    round_inputs_kernel<<<592, 256>>>(x, w_qkv, w_proj);

    // 1) QKV projection + scatter (q scaled) — cp.async + ldmatrix tf32 GEMM
    {
        dim3 grid(3*CC/128, (MTOK + 127) / 128);
        mma_gemm_nt<<<grid, 256, GEMM_SMEM>>>(b_qkv, nullptr, MTOK, 3*CC, 1);
    }

    // 2) Flash attention — tf32 tensor cores + ldmatrix
    {
        dim3 grid((NN + FA_BQ - 1) / FA_BQ, BB*HH);   // (5, 256)
        flash_mma_kernel<<<grid, 256, FA_SMEM>>>();
    }

    // 3) CLS-row outputs (full fp32)
    cls_logits_kernel<<<BB*HH, 128>>>();
    cls_out_kernel<<<(MTOK + 255) / 256, 256>>>(out + CTA_OFS, out + CTL_OFS);

    // 4) Output projection — cp.async + ldmatrix tf32 GEMM
    {
        dim3 grid(CC/128, (MTOK + 127) / 128);
        mma_gemm_nt<<<grid, 256, GEMM_SMEM>>>(b_proj, out, MTOK, CC, 2);
    }
}

// round 13
// speedup vs baseline: 1.5164x; 1.2598x over previous
#include <cuda_runtime.h>
#include <cuda_fp16.h>
#include <math.h>

// Problem constants
#define BB 16
#define HH 16
#define NN 577
#define DD 64
#define CC 1024
#define MTOK (BB*NN)            // 9232
#define PLANE (BB*HH*NN*DD)     // 9,453,568 floats per q/k/v plane
#define OUT_ELEMS (MTOK*CC)     // 9,453,568
#define CTA_OFS OUT_ELEMS
#define CTL_OFS (OUT_ELEMS + MTOK)
#define QSCALE 0.125f           // 1/sqrt(64)
#define WQKV_ELEMS (3*CC*CC)    // 3,145,728
#define WPROJ_ELEMS (CC*CC)     // 1,048,576

// Scratch (device globals: allocation-free per harness rules)
__device__ float  g_qkv[3u * PLANE];      // [3][B][H][N][D], q pre-scaled (fp32)
__device__ __half g_attn_h[OUT_ELEMS];    // [B][N][C] attention output (half)
__device__ __half g_x_h[OUT_ELEMS];       // x rounded to half
__device__ __half g_wqkv_h[WQKV_ELEMS];   // w_qkv rounded to half
__device__ __half g_wproj_h[WPROJ_ELEMS]; // w_proj rounded to half
__device__ float  g_cls_logits[BB*HH*NN]; // per-head CLS-row logits (fp32)
__device__ float  g_cls_max[BB*HH];
__device__ float  g_cls_den[BB*HH];

__device__ __forceinline__ unsigned int f2tf32(float f) {
    unsigned int r;
    asm("cvt.rna.tf32.f32 %0, %1;" : "=r"(r) : "f"(f));
    return r;
}

#define MMA_TF32(d, a, b) \
    asm("mma.sync.aligned.m16n8k8.row.col.f32.tf32.tf32.f32 " \
        "{%0,%1,%2,%3}, {%4,%5,%6,%7}, {%8,%9}, {%0,%1,%2,%3};" \
        : "+f"((d)[0]), "+f"((d)[1]), "+f"((d)[2]), "+f"((d)[3]) \
        : "r"((a)[0]), "r"((a)[1]), "r"((a)[2]), "r"((a)[3]), \
          "r"((b)[0]), "r"((b)[1]))

#define MMA_F16(d, a, b) \
    asm("mma.sync.aligned.m16n8k16.row.col.f32.f16.f16.f32 " \
        "{%0,%1,%2,%3}, {%4,%5,%6,%7}, {%8,%9}, {%0,%1,%2,%3};" \
        : "+f"((d)[0]), "+f"((d)[1]), "+f"((d)[2]), "+f"((d)[3]) \
        : "r"((a)[0]), "r"((a)[1]), "r"((a)[2]), "r"((a)[3]), \
          "r"((b)[0]), "r"((b)[1]))

#define LDSM_X4(r0, r1, r2, r3, addr) \
    asm volatile("ldmatrix.sync.aligned.m8n8.x4.shared.b16 {%0,%1,%2,%3}, [%4];" \
        : "=r"(r0), "=r"(r1), "=r"(r2), "=r"(r3) : "r"(addr))

#define CP_ASYNC16(smem_u32, gptr) \
    asm volatile("cp.async.cg.shared.global [%0], [%1], 16;" :: "r"(smem_u32), "l"(gptr) : "memory")
#define CP_COMMIT()  asm volatile("cp.async.commit_group;" ::: "memory")
#define CP_WAIT1()   asm volatile("cp.async.wait_group 1;" ::: "memory")
#define CP_WAIT0()   asm volatile("cp.async.wait_group 0;" ::: "memory")

// ---------------------------------------------------------------------------
// Pre-round inputs to half (one elementwise pass).
// ---------------------------------------------------------------------------
__global__ void round_inputs_kernel(const float* __restrict__ x,
                                    const float* __restrict__ wq,
                                    const float* __restrict__ wp)
{
    const int total = OUT_ELEMS + WQKV_ELEMS + WPROJ_ELEMS;
    for (int i = blockIdx.x * blockDim.x + threadIdx.x; i < total;
         i += gridDim.x * blockDim.x) {
        if (i < OUT_ELEMS) {
            g_x_h[i] = __float2half_rn(x[i]);
        } else if (i < OUT_ELEMS + WQKV_ELEMS) {
            int j = i - OUT_ELEMS;
            g_wqkv_h[j] = __float2half_rn(wq[j]);
        } else {
            int j = i - OUT_ELEMS - WQKV_ELEMS;
            g_wproj_h[j] = __float2half_rn(wp[j]);
        }
    }
}

// ---------------------------------------------------------------------------
// fp16 tensor-core GEMM (m16n8k16), cp.async double-buffered, ldmatrix.
// C[m,n] = sum_k A[m,k] * W[n,k] (+bias), fp32 accumulate. K = 1024.
// BM=BN=128, BK=32 halves (64 B/row data, padded to 80 B -> all-bank LDSM).
// 256 threads (8 warps as 4m x 2n, warp tile 32x64).
// mode 1: A=g_x_h, W=g_wqkv_h, scatter into g_qkv (q scaled)
// mode 2: A=g_attn_h, W=g_wproj_h, plain epilogue into Cout
// ---------------------------------------------------------------------------
#define HROW_B   80                     // bytes per smem row (64 data + 16 pad)
#define HTILE_B  (128 * HROW_B)         // 10240 B per operand tile
#define HGEMM_SMEM (4 * HTILE_B)        // 2 stages x (A + W) = 40960 B

__global__ __launch_bounds__(256) void hgemm_nt(
    const float* __restrict__ bias, float* __restrict__ Cout,
    int M, int N, int mode)
{
    extern __shared__ unsigned char smraw[];
    const int K = 1024;
    const int NT = 32;

    const __half* Abase = (mode == 2) ? g_attn_h : g_x_h;
    const __half* Wbase = (mode == 2) ? g_wproj_h : g_wqkv_h;

    const int tid  = threadIdx.x;
    const int lane = tid & 31;
    const int warp = tid >> 5;
    const int wm   = warp & 3;
    const int wn   = warp >> 2;
    const int bm   = blockIdx.y * 128;
    const int bn   = blockIdx.x * 128;

    float acc[2][8][4];
    #pragma unroll
    for (int i = 0; i < 2; i++)
        #pragma unroll
        for (int j = 0; j < 8; j++)
            #pragma unroll
            for (int e = 0; e < 4; e++) acc[i][j][e] = 0.f;

    const int g  = lane >> 2;
    const int tg = lane & 3;

    // cp.async coords: 128 rows x 4 chunks(16B=8 halves) per operand; 2/thread
    unsigned int soff[2];
    const __half* aptr[2];
    const __half* wptr[2];
    #pragma unroll
    for (int i = 0; i < 2; i++) {
        int p   = i * 256 + tid;
        int row = p >> 2;
        int c16 = p & 3;
        soff[i] = (unsigned int)(row * HROW_B + c16 * 16);
        int ar  = bm + row;
        aptr[i] = Abase + (size_t)((ar < M) ? ar : (M - 1)) * K + c16 * 8;
        wptr[i] = Wbase + (size_t)(bn + row) * K + c16 * 8;
    }

    const unsigned int sbase = (unsigned int)__cvta_generic_to_shared(smraw);

    // ldmatrix lane addresses: lanes 0-7 rows 0-7 (k-half 0), 8-15 rows 8-15,
    // 16-23 rows 0-7 (+16B), 24-31 rows 8-15 (+16B) -> frags in a0..a3 order.
    const int lrow16 = lane & 15;
    const int khalf  = (lane >> 4) * 16;
    const unsigned int a_off0 = (unsigned int)((wm * 32 +  0 + lrow16) * HROW_B + khalf);
    const unsigned int a_off1 = (unsigned int)((wm * 32 + 16 + lrow16) * HROW_B + khalf);
    unsigned int b_off[4];
    #pragma unroll
    for (int p = 0; p < 4; p++)
        b_off[p] = (unsigned int)((wn * 64 + p * 16 + lrow16) * HROW_B + khalf);

    // prologue: tile 0 -> stage 0
    {
        unsigned int as = sbase;
        unsigned int ws = sbase + HTILE_B;
        #pragma unroll
        for (int i = 0; i < 2; i++) {
            CP_ASYNC16(as + soff[i], aptr[i]);
            CP_ASYNC16(ws + soff[i], wptr[i]);
        }
        CP_COMMIT();
    }

    for (int t = 0; t < NT; t++) {
        const int s = t & 1;
        if (t + 1 < NT) {
            const int s2 = s ^ 1;
            const int k0 = (t + 1) * 32;
            unsigned int as = sbase + (unsigned)s2 * 2 * HTILE_B;
            unsigned int ws = as + HTILE_B;
            #pragma unroll
            for (int i = 0; i < 2; i++) {
                CP_ASYNC16(as + soff[i], aptr[i] + k0);
                CP_ASYNC16(ws + soff[i], wptr[i] + k0);
            }
            CP_COMMIT();
            CP_WAIT1();
        } else {
            CP_WAIT0();
        }
        __syncthreads();

        const unsigned int as_u32 = sbase + (unsigned)s * 2 * HTILE_B;
        const unsigned int ws_u32 = as_u32 + HTILE_B;

        #pragma unroll
        for (int ks = 0; ks < 2; ks++) {
            const int kb = ks * 32;     // byte offset of this k16 step in row
            unsigned int af[2][4], bf[8][2];
            LDSM_X4(af[0][0], af[0][1], af[0][2], af[0][3], as_u32 + a_off0 + kb);
            LDSM_X4(af[1][0], af[1][1], af[1][2], af[1][3], as_u32 + a_off1 + kb);
            #pragma unroll
            for (int p = 0; p < 4; p++) {
                LDSM_X4(bf[2*p][0], bf[2*p+1][0], bf[2*p][1], bf[2*p+1][1],
                        ws_u32 + b_off[p] + kb);
            }
            #pragma unroll
            for (int mt = 0; mt < 2; mt++)
                #pragma unroll
                for (int nt = 0; nt < 8; nt++)
                    MMA_F16(acc[mt][nt], af[mt], bf[nt]);
        }
        __syncthreads();   // stage reads done before tile t+2 overwrites it
    }

    // Epilogue. c-elem e: row += (e>=2)*8, col = tg*2 + (e&1)
    #pragma unroll
    for (int mt = 0; mt < 2; mt++) {
        #pragma unroll
        for (int eh = 0; eh < 2; eh++) {
            int m = bm + wm * 32 + mt * 16 + g + eh * 8;
            if (m >= M) continue;
            if (mode == 1) {
                int b_  = m / NN;
                int tok = m - b_ * NN;
                #pragma unroll
                for (int nt = 0; nt < 8; nt++) {
                    #pragma unroll
                    for (int ec = 0; ec < 2; ec++) {
                        int n = bn + wn * 64 + nt * 8 + tg * 2 + ec;
                        float v = acc[mt][nt][eh * 2 + ec] + bias[n];
                        int which = n >> 10;
                        int rest  = n & 1023;
                        int h = rest >> 6;
                        int d = rest & 63;
                        if (which == 0) v *= QSCALE;
                        g_qkv[(size_t)which * PLANE + (((size_t)(b_ * HH + h) * NN + tok) << 6) + d] = v;
                    }
                }
            } else {
                #pragma unroll
                for (int nt = 0; nt < 8; nt++) {
                    int n = bn + wn * 64 + nt * 8 + tg * 2;
                    float2 v = make_float2(acc[mt][nt][eh * 2 + 0] + bias[n],
                                           acc[mt][nt][eh * 2 + 1] + bias[n + 1]);
                    *(float2*)(Cout + (size_t)m * N + n) = v;
                }
            }
        }
    }
}

// ---------------------------------------------------------------------------
// Tensor-core flash attention (tf32 mma.sync), ldmatrix for Q/K/P fragments.
// Grid (5 q-tiles of 128, 256 bh), 256 threads = 8 warps x 16 q-rows.
// Epilogue writes g_attn_h (half) for the fp16 projection GEMM.
// ---------------------------------------------------------------------------
#define FA_SROW 68
#define FA_BQ   128
#define KS_OFF  (FA_BQ * FA_SROW)
#define VS_OFF  (KS_OFF + 64 * FA_SROW)
#define PS_OFF  (VS_OFF + 64 * FA_SROW)
#define FA_SMEM ((PS_OFF + FA_BQ * FA_SROW) * 4)

__global__ __launch_bounds__(256) void flash_mma_kernel()
{
    extern __shared__ unsigned int smu[];
    unsigned int* Qs = smu;                      // [128][68] tf32
    unsigned int* Ks = smu + KS_OFF;             // [64][68]  tf32
    unsigned int* Vs = smu + VS_OFF;             // [64][68]  tf32
    unsigned int* Ps = smu + PS_OFF;             // [128][68] tf32

    const int tid  = threadIdx.x;
    const int lane = tid & 31;
    const int warp = tid >> 5;
    const int g    = lane >> 2;
    const int tg   = lane & 3;
    const int qt   = blockIdx.x;          // 0..4
    const int bh   = blockIdx.y;          // 0..255
    const int q0g  = qt * FA_BQ;
    const int wr   = warp * 16;

    const float* Qg = g_qkv + (size_t)bh * NN * DD;
    const float* Kg = g_qkv + (size_t)PLANE + (size_t)bh * NN * DD;
    const float* Vg = g_qkv + 2u * (size_t)PLANE + (size_t)bh * NN * DD;

    // Load Q tile (tf32). 128 rows x 16 float4 = 2048, 8 per thread.
    #pragma unroll
    for (int i = 0; i < 8; i++) {
        int p   = i * 256 + tid;
        int row = p >> 4;
        int c4  = (p & 15) << 2;
        int tok = q0g + row; if (tok > NN - 1) tok = NN - 1;   // clamp (rows >= NN unused)
        float4 v = *(const float4*)(Qg + (size_t)tok * DD + c4);
        *(uint4*)(Qs + row * FA_SROW + c4) =
            make_uint4(f2tf32(v.x), f2tf32(v.y), f2tf32(v.z), f2tf32(v.w));
    }

    const unsigned int smu_base = (unsigned int)__cvta_generic_to_shared(smu);
    const int a_lrow = lane & 15;
    const int a_lcol = (lane >> 4) << 2;
    const unsigned int q_addr = smu_base + (((wr + a_lrow) * FA_SROW) + a_lcol) * 4;
    const unsigned int p_addr = smu_base + ((PS_OFF + (wr + a_lrow) * FA_SROW) + a_lcol) * 4;
    const int b_lrow = ((lane >> 4) << 3) + (lane & 7);
    const int b_lcol = ((lane >> 3) & 1) << 2;
    const unsigned int k_addr = smu_base + ((KS_OFF + b_lrow * FA_SROW) + b_lcol) * 4;

    float oacc[8][4];
    #pragma unroll
    for (int nt = 0; nt < 8; nt++)
        #pragma unroll
        for (int e = 0; e < 4; e++) oacc[nt][e] = 0.f;
    float m_i[2] = { -1e30f, -1e30f };
    float l_i[2] = { 0.f, 0.f };

    for (int kt = 0; kt < 10; kt++) {
        const int k0g = kt * 64;
        __syncthreads();   // prior-iteration Ks/Vs reads complete (also covers Q store)

        // Load K/V tiles (tf32). 64 rows x 16 float4 each, 4+4 per thread.
        #pragma unroll
        for (int i = 0; i < 4; i++) {
            int p   = i * 256 + tid;
            int row = p >> 4;
            int c4  = (p & 15) << 2;
            int tok = k0g + row; if (tok > NN - 1) tok = NN - 1;  // clamp (masked later)
            float4 kv = *(const float4*)(Kg + (size_t)tok * DD + c4);
            float4 vv = *(const float4*)(Vg + (size_t)tok * DD + c4);
            *(uint4*)(Ks + row * FA_SROW + c4) =
                make_uint4(f2tf32(kv.x), f2tf32(kv.y), f2tf32(kv.z), f2tf32(kv.w));
            *(uint4*)(Vs + row * FA_SROW + c4) =
                make_uint4(f2tf32(vv.x), f2tf32(vv.y), f2tf32(vv.z), f2tf32(vv.w));
        }
        __syncthreads();

        // ---- S = Q K^T ----
        float sacc[8][4];
        #pragma unroll
        for (int nt = 0; nt < 8; nt++)
            #pragma unroll
            for (int e = 0; e < 4; e++) sacc[nt][e] = 0.f;

        #pragma unroll
        for (int ks = 0; ks < 8; ks++) {
            const int kb = ks << 3;
            unsigned int af[4], bf[8][2];
            LDSM_X4(af[0], af[1], af[2], af[3], q_addr + kb * 4);
            #pragma unroll
            for (int p = 0; p < 4; p++) {
                LDSM_X4(bf[2*p][0], bf[2*p][1], bf[2*p+1][0], bf[2*p+1][1],
                        k_addr + (p * 16 * FA_SROW + kb) * 4);
            }
            #pragma unroll
            for (int nt = 0; nt < 8; nt++)
                MMA_TF32(sacc[nt], af, bf[nt]);
        }

        // ---- online softmax on fragments ----
        #pragma unroll
        for (int eh = 0; eh < 2; eh++) {
            float mloc = -1e30f;
            #pragma unroll
            for (int nt = 0; nt < 8; nt++) {
                #pragma unroll
                for (int ec = 0; ec < 2; ec++) {
                    int key = k0g + nt * 8 + tg * 2 + ec;
                    if (key >= NN) sacc[nt][eh * 2 + ec] = -1e30f;
                    mloc = fmaxf(mloc, sacc[nt][eh * 2 + ec]);
                }
            }
            mloc = fmaxf(mloc, __shfl_xor_sync(0xffffffffu, mloc, 1));
            mloc = fmaxf(mloc, __shfl_xor_sync(0xffffffffu, mloc, 2));
            float m_new = fmaxf(m_i[eh], mloc);
            float alpha = __expf(m_i[eh] - m_new);

            float psum = 0.f;
            int prow = (wr + g + eh * 8) * FA_SROW;
            #pragma unroll
            for (int nt = 0; nt < 8; nt++) {
                float p0 = __expf(sacc[nt][eh * 2 + 0] - m_new);
                float p1 = __expf(sacc[nt][eh * 2 + 1] - m_new);
                psum += p0 + p1;
                *(uint2*)(Ps + prow + nt * 8 + tg * 2) = make_uint2(f2tf32(p0), f2tf32(p1));
            }
            psum += __shfl_xor_sync(0xffffffffu, psum, 1);
            psum += __shfl_xor_sync(0xffffffffu, psum, 2);
            l_i[eh] = l_i[eh] * alpha + psum;
            m_i[eh] = m_new;
            #pragma unroll
            for (int nt = 0; nt < 8; nt++) {
                oacc[nt][eh * 2 + 0] *= alpha;
                oacc[nt][eh * 2 + 1] *= alpha;
            }
        }
        __syncwarp();   // Ps strip visible within warp

        // ---- O += P V : A = P (LDSM), B = Vs (scalar, transposed access) ----
        #pragma unroll
        for (int ks = 0; ks < 8; ks++) {
            const int kb = ks << 3;
            unsigned int af[4], bf[8][2];
            LDSM_X4(af[0], af[1], af[2], af[3], p_addr + kb * 4);
            #pragma unroll
            for (int nt = 0; nt < 8; nt++) {
                bf[nt][0] = Vs[(kb + tg) * FA_SROW + nt * 8 + g];
                bf[nt][1] = Vs[(kb + tg + 4) * FA_SROW + nt * 8 + g];
            }
            #pragma unroll
            for (int nt = 0; nt < 8; nt++)
                MMA_TF32(oacc[nt], af, bf[nt]);
        }
        __syncwarp();   // Ps reads done before next-iter overwrite
    }

    // ---- write O as half (consumed by fp16 projection GEMM) ----
    const int b_ = bh >> 4, hd = bh & 15;
    #pragma unroll
    for (int eh = 0; eh < 2; eh++) {
        int tok = q0g + wr + g + eh * 8;
        if (tok >= NN) continue;
        float inv = 1.f / l_i[eh];
        __half* o = g_attn_h + ((size_t)b_ * NN + tok) * CC + hd * DD;
        #pragma unroll
        for (int nt = 0; nt < 8; nt++) {
            __half2 hv = __floats2half2_rn(oacc[nt][eh * 2 + 0] * inv,
                                           oacc[nt][eh * 2 + 1] * inv);
            *(__half2*)(o + nt * 8 + tg * 2) = hv;
        }
    }
}

// ---------------------------------------------------------------------------
// CLS-row logits per (b,h): logits[m] = q0 . k[m]; also max & softmax denom
// ---------------------------------------------------------------------------
__global__ __launch_bounds__(128) void cls_logits_kernel()
{
    __shared__ float q0s[64];
    __shared__ float red[128];
    const int bh  = blockIdx.x;
    const int tid = threadIdx.x;
    const float* Qg = g_qkv + (size_t)bh * NN * DD;            // q already scaled
    const float* Kg = g_qkv + (size_t)PLANE + (size_t)bh * NN * DD;

    if (tid < 64) q0s[tid] = Qg[tid];
    __syncthreads();

    float lg[5];
    float mloc = -1e30f;
    #pragma unroll
    for (int i = 0; i < 5; i++) {
        int m = tid + i*128;
        float s = -1e30f;
        if (m < NN) {
            s = 0.f;
            const float* kr = Kg + (size_t)m * DD;
            #pragma unroll
            for (int d4 = 0; d4 < 64; d4 += 4) {
                float4 k4 = *(const float4*)(kr + d4);
                s += q0s[d4]*k4.x + q0s[d4+1]*k4.y + q0s[d4+2]*k4.z + q0s[d4+3]*k4.w;
            }
            g_cls_logits[(size_t)bh * NN + m] = s;
        }
        lg[i] = s;
        mloc = fmaxf(mloc, s);
    }

    red[tid] = mloc; __syncthreads();
    for (int o = 64; o > 0; o >>= 1) {
        if (tid < o) red[tid] = fmaxf(red[tid], red[tid+o]);
        __syncthreads();
    }
    float mx = red[0];
    __syncthreads();

    float se = 0.f;
    #pragma unroll
    for (int i = 0; i < 5; i++)
        if (lg[i] > -1e29f) se += __expf(lg[i] - mx);
    red[tid] = se; __syncthreads();
    for (int o = 64; o > 0; o >>= 1) {
        if (tid < o) red[tid] += red[tid+o];
        __syncthreads();
    }
    if (tid == 0) { g_cls_max[bh] = mx; g_cls_den[bh] = red[0]; }
}

// Head-mean of CLS logits and CLS attention
__global__ void cls_out_kernel(float* __restrict__ out_cta, float* __restrict__ out_ctl)
{
    int idx = blockIdx.x * blockDim.x + threadIdx.x;
    if (idx >= MTOK) return;
    int b_ = idx / NN;
    int m  = idx - b_ * NN;
    float sl = 0.f, sa = 0.f;
    #pragma unroll
    for (int h = 0; h < HH; h++) {
        int bh = b_ * HH + h;
        float l = g_cls_logits[(size_t)bh * NN + m];
        sl += l;
        sa += __expf(l - g_cls_max[bh]) / g_cls_den[bh];
    }
    out_ctl[idx] = sl * (1.f / 16.f);
    out_cta[idx] = sa * (1.f / 16.f);
}

// ---------------------------------------------------------------------------
extern "C" void kernel_launch(void* const* d_in, const int* in_sizes, int n_in,
                              void* d_out, int out_size)
{
    const float* x      = (const float*)d_in[0];
    const float* w_qkv  = (const float*)d_in[1];
    const float* b_qkv  = (const float*)d_in[2];
    const float* w_proj = (const float*)d_in[3];
    const float* b_proj = (const float*)d_in[4];
    float* out = (float*)d_out;

    cudaFuncSetAttribute(hgemm_nt,
                         cudaFuncAttributeMaxDynamicSharedMemorySize, HGEMM_SMEM);
    cudaFuncSetAttribute(flash_mma_kernel,
                         cudaFuncAttributeMaxDynamicSharedMemorySize, FA_SMEM);

    // 0) Pre-round x / w_qkv / w_proj to half
    round_inputs_kernel<<<592, 256>>>(x, w_qkv, w_proj);

    // 1) QKV projection + scatter (q scaled) — fp16 m16n8k16 GEMM
    {
        dim3 grid(3*CC/128, (MTOK + 127) / 128);
        hgemm_nt<<<grid, 256, HGEMM_SMEM>>>(b_qkv, nullptr, MTOK, 3*CC, 1);
    }

    // 2) Flash attention — tf32 mma.sync + ldmatrix
    {
        dim3 grid((NN + FA_BQ - 1) / FA_BQ, BB*HH);   // (5, 256)
        flash_mma_kernel<<<grid, 256, FA_SMEM>>>();
    }

    // 3) CLS-row outputs (full fp32)
    cls_logits_kernel<<<BB*HH, 128>>>();
    cls_out_kernel<<<(MTOK + 255) / 256, 256>>>(out + CTA_OFS, out + CTL_OFS);

    // 4) Output projection — fp16 m16n8k16 GEMM
    {
        dim3 grid(CC/128, (MTOK + 127) / 128);
        hgemm_nt<<<grid, 256, HGEMM_SMEM>>>(b_proj, out, MTOK, CC, 2);
    }
}

// round 15
// speedup vs baseline: 1.8425x; 1.2150x over previous
#include <cuda_runtime.h>
#include <cuda_fp16.h>
#include <math.h>

// Problem constants
#define BB 16
#define HH 16
#define NN 577
#define DD 64
#define CC 1024
#define MTOK (BB*NN)            // 9232
#define PLANE (BB*HH*NN*DD)     // 9,453,568 per q/k/v plane
#define OUT_ELEMS (MTOK*CC)     // 9,453,568
#define CTA_OFS OUT_ELEMS
#define CTL_OFS (OUT_ELEMS + MTOK)
#define QSCALE 0.125f           // 1/sqrt(64)
#define WQKV_ELEMS (3*CC*CC)    // 3,145,728
#define WPROJ_ELEMS (CC*CC)     // 1,048,576

// Scratch (device globals: allocation-free per harness rules)
__device__ __half g_qkv_h[3u * PLANE];    // [3][B][H][N][D] half (flash inputs)
__device__ float  g_k32[PLANE];           // K plane fp32 (CLS path)
__device__ float  g_q0[BB*HH*DD];         // q row-0 fp32 per (b,h) (CLS path)
__device__ __half g_attn_h[OUT_ELEMS];    // [B][N][C] attention output (half)
__device__ __half g_x_h[OUT_ELEMS];       // x rounded to half
__device__ __half g_wqkv_h[WQKV_ELEMS];   // w_qkv rounded to half
__device__ __half g_wproj_h[WPROJ_ELEMS]; // w_proj rounded to half
__device__ float  g_cls_logits[BB*HH*NN]; // per-head CLS-row logits (fp32)
__device__ float  g_cls_max[BB*HH];
__device__ float  g_cls_den[BB*HH];

#define MMA_F16(d, a, b) \
    asm("mma.sync.aligned.m16n8k16.row.col.f32.f16.f16.f32 " \
        "{%0,%1,%2,%3}, {%4,%5,%6,%7}, {%8,%9}, {%0,%1,%2,%3};" \
        : "+f"((d)[0]), "+f"((d)[1]), "+f"((d)[2]), "+f"((d)[3]) \
        : "r"((a)[0]), "r"((a)[1]), "r"((a)[2]), "r"((a)[3]), \
          "r"((b)[0]), "r"((b)[1]))

#define LDSM_X4(r0, r1, r2, r3, addr) \
    asm volatile("ldmatrix.sync.aligned.m8n8.x4.shared.b16 {%0,%1,%2,%3}, [%4];" \
        : "=r"(r0), "=r"(r1), "=r"(r2), "=r"(r3) : "r"(addr))

#define LDSM_X4_T(r0, r1, r2, r3, addr) \
    asm volatile("ldmatrix.sync.aligned.m8n8.x4.trans.shared.b16 {%0,%1,%2,%3}, [%4];" \
        : "=r"(r0), "=r"(r1), "=r"(r2), "=r"(r3) : "r"(addr))

#define CP_ASYNC16(smem_u32, gptr) \
    asm volatile("cp.async.cg.shared.global [%0], [%1], 16;" :: "r"(smem_u32), "l"(gptr) : "memory")
#define CP_COMMIT()  asm volatile("cp.async.commit_group;" ::: "memory")
#define CP_WAIT1()   asm volatile("cp.async.wait_group 1;" ::: "memory")
#define CP_WAIT0()   asm volatile("cp.async.wait_group 0;" ::: "memory")

// ---------------------------------------------------------------------------
// Pre-round inputs to half (one elementwise pass).
// ---------------------------------------------------------------------------
__global__ void round_inputs_kernel(const float* __restrict__ x,
                                    const float* __restrict__ wq,
                                    const float* __restrict__ wp)
{
    const int total = OUT_ELEMS + WQKV_ELEMS + WPROJ_ELEMS;
    for (int i = blockIdx.x * blockDim.x + threadIdx.x; i < total;
         i += gridDim.x * blockDim.x) {
        if (i < OUT_ELEMS) {
            g_x_h[i] = __float2half_rn(x[i]);
        } else if (i < OUT_ELEMS + WQKV_ELEMS) {
            int j = i - OUT_ELEMS;
            g_wqkv_h[j] = __float2half_rn(wq[j]);
        } else {
            int j = i - OUT_ELEMS - WQKV_ELEMS;
            g_wproj_h[j] = __float2half_rn(wp[j]);
        }
    }
}

// ---------------------------------------------------------------------------
// fp16 tensor-core GEMM (m16n8k16), cp.async double-buffered, ldmatrix.
// C[m,n] = sum_k A[m,k] * W[n,k] (+bias), fp32 accumulate. K = 1024.
// BM=BN=128, BK=32 halves (64 B/row data, padded to 80 B -> all-bank LDSM).
// mode 1: A=g_x_h, W=g_wqkv_h, scatter HALF into g_qkv_h (+ fp32 K plane/q0)
// mode 2: A=g_attn_h, W=g_wproj_h, plain epilogue into Cout
// ---------------------------------------------------------------------------
#define HROW_B   80
#define HTILE_B  (128 * HROW_B)
#define HGEMM_SMEM (4 * HTILE_B)        // 40960 B

__global__ __launch_bounds__(256) void hgemm_nt(
    const float* __restrict__ bias, float* __restrict__ Cout,
    int M, int N, int mode)
{
    extern __shared__ unsigned char smraw[];
    const int K = 1024;
    const int NT = 32;

    const __half* Abase = (mode == 2) ? g_attn_h : g_x_h;
    const __half* Wbase = (mode == 2) ? g_wproj_h : g_wqkv_h;

    const int tid  = threadIdx.x;
    const int lane = tid & 31;
    const int warp = tid >> 5;
    const int wm   = warp & 3;
    const int wn   = warp >> 2;
    const int bm   = blockIdx.y * 128;
    const int bn   = blockIdx.x * 128;

    float acc[2][8][4];
    #pragma unroll
    for (int i = 0; i < 2; i++)
        #pragma unroll
        for (int j = 0; j < 8; j++)
            #pragma unroll
            for (int e = 0; e < 4; e++) acc[i][j][e] = 0.f;

    const int g  = lane >> 2;
    const int tg = lane & 3;

    unsigned int soff[2];
    const __half* aptr[2];
    const __half* wptr[2];
    #pragma unroll
    for (int i = 0; i < 2; i++) {
        int p   = i * 256 + tid;
        int row = p >> 2;
        int c16 = p & 3;
        soff[i] = (unsigned int)(row * HROW_B + c16 * 16);
        int ar  = bm + row;
        aptr[i] = Abase + (size_t)((ar < M) ? ar : (M - 1)) * K + c16 * 8;
        wptr[i] = Wbase + (size_t)(bn + row) * K + c16 * 8;
    }

    const unsigned int sbase = (unsigned int)__cvta_generic_to_shared(smraw);

    const int lrow16 = lane & 15;
    const int khalf  = (lane >> 4) * 16;
    const unsigned int a_off0 = (unsigned int)((wm * 32 +  0 + lrow16) * HROW_B + khalf);
    const unsigned int a_off1 = (unsigned int)((wm * 32 + 16 + lrow16) * HROW_B + khalf);
    unsigned int b_off[4];
    #pragma unroll
    for (int p = 0; p < 4; p++)
        b_off[p] = (unsigned int)((wn * 64 + p * 16 + lrow16) * HROW_B + khalf);

    {
        unsigned int as = sbase;
        unsigned int ws = sbase + HTILE_B;
        #pragma unroll
        for (int i = 0; i < 2; i++) {
            CP_ASYNC16(as + soff[i], aptr[i]);
            CP_ASYNC16(ws + soff[i], wptr[i]);
        }
        CP_COMMIT();
    }

    for (int t = 0; t < NT; t++) {
        const int s = t & 1;
        if (t + 1 < NT) {
            const int s2 = s ^ 1;
            const int k0 = (t + 1) * 32;
            unsigned int as = sbase + (unsigned)s2 * 2 * HTILE_B;
            unsigned int ws = as + HTILE_B;
            #pragma unroll
            for (int i = 0; i < 2; i++) {
                CP_ASYNC16(as + soff[i], aptr[i] + k0);
                CP_ASYNC16(ws + soff[i], wptr[i] + k0);
            }
            CP_COMMIT();
            CP_WAIT1();
        } else {
            CP_WAIT0();
        }
        __syncthreads();

        const unsigned int as_u32 = sbase + (unsigned)s * 2 * HTILE_B;
        const unsigned int ws_u32 = as_u32 + HTILE_B;

        #pragma unroll
        for (int ks = 0; ks < 2; ks++) {
            const int kb = ks * 32;
            unsigned int af[2][4], bf[8][2];
            LDSM_X4(af[0][0], af[0][1], af[0][2], af[0][3], as_u32 + a_off0 + kb);
            LDSM_X4(af[1][0], af[1][1], af[1][2], af[1][3], as_u32 + a_off1 + kb);
            #pragma unroll
            for (int p = 0; p < 4; p++) {
                LDSM_X4(bf[2*p][0], bf[2*p+1][0], bf[2*p][1], bf[2*p+1][1],
                        ws_u32 + b_off[p] + kb);
            }
            #pragma unroll
            for (int mt = 0; mt < 2; mt++)
                #pragma unroll
                for (int nt = 0; nt < 8; nt++)
                    MMA_F16(acc[mt][nt], af[mt], bf[nt]);
        }
        __syncthreads();
    }

    #pragma unroll
    for (int mt = 0; mt < 2; mt++) {
        #pragma unroll
        for (int eh = 0; eh < 2; eh++) {
            int m = bm + wm * 32 + mt * 16 + g + eh * 8;
            if (m >= M) continue;
            if (mode == 1) {
                int b_  = m / NN;
                int tok = m - b_ * NN;
                #pragma unroll
                for (int nt = 0; nt < 8; nt++) {
                    #pragma unroll
                    for (int ec = 0; ec < 2; ec++) {
                        int n = bn + wn * 64 + nt * 8 + tg * 2 + ec;
                        float v = acc[mt][nt][eh * 2 + ec] + bias[n];
                        int which = n >> 10;
                        int rest  = n & 1023;
                        int h = rest >> 6;
                        int d = rest & 63;
                        if (which == 0) v *= QSCALE;
                        size_t idx = (((size_t)(b_ * HH + h) * NN + tok) << 6) + d;
                        g_qkv_h[(size_t)which * PLANE + idx] = __float2half_rn(v);
                        if (which == 1) g_k32[idx] = v;
                        else if (which == 0 && tok == 0) g_q0[(b_ * HH + h) * DD + d] = v;
                    }
                }
            } else {
                #pragma unroll
                for (int nt = 0; nt < 8; nt++) {
                    int n = bn + wn * 64 + nt * 8 + tg * 2;
                    float2 v = make_float2(acc[mt][nt][eh * 2 + 0] + bias[n],
                                           acc[mt][nt][eh * 2 + 1] + bias[n + 1]);
                    *(float2*)(Cout + (size_t)m * N + n) = v;
                }
            }
        }
    }
}

// ---------------------------------------------------------------------------
// fp16 tensor-core flash attention (m16n8k16).
// Grid (5 q-tiles of 128, 256 bh), 256 threads = 8 warps x 16 q-rows.
// smem rows 144 B (128 data + 16 pad -> LDSM rows tile all banks).
// S = Q K^T (non-trans B over K rows), PV with V via ldmatrix.trans.
// ---------------------------------------------------------------------------
#define FH_ROW  144
#define FQ_OFF  0
#define FK_OFF  (128 * FH_ROW)
#define FV_OFF  (FK_OFF + 64 * FH_ROW)
#define FP_OFF  (FV_OFF + 64 * FH_ROW)
#define FH_SMEM (FP_OFF + 128 * FH_ROW)   // 55296 B

__global__ __launch_bounds__(256) void flash_h_kernel()
{
    extern __shared__ unsigned char fsm[];

    const int tid  = threadIdx.x;
    const int lane = tid & 31;
    const int warp = tid >> 5;
    const int g    = lane >> 2;
    const int tg   = lane & 3;
    const int qt   = blockIdx.x;          // 0..4
    const int bh   = blockIdx.y;          // 0..255
    const int q0g  = qt * 128;
    const int wr   = warp * 16;

    const __half* Qg = g_qkv_h + (size_t)bh * NN * DD;
    const __half* Kg = g_qkv_h + (size_t)PLANE + (size_t)bh * NN * DD;
    const __half* Vg = g_qkv_h + 2u * (size_t)PLANE + (size_t)bh * NN * DD;

    // Load Q tile: 128 rows x 8 chunks(16B) = 1024, 4 per thread.
    #pragma unroll
    for (int i = 0; i < 4; i++) {
        int p   = i * 256 + tid;
        int row = p >> 3;
        int c16 = p & 7;
        int tok = q0g + row; if (tok > NN - 1) tok = NN - 1;   // clamp (rows >= NN unused)
        *(uint4*)(fsm + FQ_OFF + row * FH_ROW + c16 * 16) =
            *(const uint4*)(Qg + (size_t)tok * DD + c16 * 8);
    }

    const unsigned int sb = (unsigned int)__cvta_generic_to_shared(fsm);
    const int lrow16 = lane & 15;
    const int kh16   = (lane >> 4) * 16;
    const unsigned int q_addr = sb + FQ_OFF + (unsigned)((wr + lrow16) * FH_ROW + kh16);
    const unsigned int p_addr = sb + FP_OFF + (unsigned)((wr + lrow16) * FH_ROW + kh16);
    const unsigned int k_addr = sb + FK_OFF + (unsigned)(lrow16 * FH_ROW + kh16);
    const int vrow = (lane & 7) + ((lane >> 3) & 1) * 8;
    const unsigned int v_addr = sb + FV_OFF + (unsigned)(vrow * FH_ROW + kh16);

    float oacc[8][4];
    #pragma unroll
    for (int nt = 0; nt < 8; nt++)
        #pragma unroll
        for (int e = 0; e < 4; e++) oacc[nt][e] = 0.f;
    float m_i[2] = { -1e30f, -1e30f };
    float l_i[2] = { 0.f, 0.f };

    for (int kt = 0; kt < 10; kt++) {
        const int k0g = kt * 64;
        __syncthreads();   // prior-iteration K/V reads complete (also covers Q store)

        // Load K/V tiles: 64 rows x 8 chunks each, 2+2 per thread.
        #pragma unroll
        for (int i = 0; i < 2; i++) {
            int p   = i * 256 + tid;
            int row = p >> 3;
            int c16 = p & 7;
            int tok = k0g + row; if (tok > NN - 1) tok = NN - 1;  // clamp (masked later)
            *(uint4*)(fsm + FK_OFF + row * FH_ROW + c16 * 16) =
                *(const uint4*)(Kg + (size_t)tok * DD + c16 * 8);
            *(uint4*)(fsm + FV_OFF + row * FH_ROW + c16 * 16) =
                *(const uint4*)(Vg + (size_t)tok * DD + c16 * 8);
        }
        __syncthreads();

        // ---- S = Q K^T : 16 q-rows x 64 keys per warp, 4 k16 steps ----
        float sacc[8][4];
        #pragma unroll
        for (int nt = 0; nt < 8; nt++)
            #pragma unroll
            for (int e = 0; e < 4; e++) sacc[nt][e] = 0.f;

        #pragma unroll
        for (int ks = 0; ks < 4; ks++) {
            const int kb = ks * 32;   // 16 halves = 32 bytes along d
            unsigned int af[4], bf[8][2];
            LDSM_X4(af[0], af[1], af[2], af[3], q_addr + kb);
            #pragma unroll
            for (int p = 0; p < 4; p++) {
                LDSM_X4(bf[2*p][0], bf[2*p+1][0], bf[2*p][1], bf[2*p+1][1],
                        k_addr + p * 16 * FH_ROW + kb);
            }
            #pragma unroll
            for (int nt = 0; nt < 8; nt++)
                MMA_F16(sacc[nt], af, bf[nt]);
        }

        // ---- online softmax on fragments (rows wr+g, wr+g+8) ----
        #pragma unroll
        for (int eh = 0; eh < 2; eh++) {
            float mloc = -1e30f;
            #pragma unroll
            for (int nt = 0; nt < 8; nt++) {
                #pragma unroll
                for (int ec = 0; ec < 2; ec++) {
                    int key = k0g + nt * 8 + tg * 2 + ec;
                    if (key >= NN) sacc[nt][eh * 2 + ec] = -1e30f;
                    mloc = fmaxf(mloc, sacc[nt][eh * 2 + ec]);
                }
            }
            mloc = fmaxf(mloc, __shfl_xor_sync(0xffffffffu, mloc, 1));
            mloc = fmaxf(mloc, __shfl_xor_sync(0xffffffffu, mloc, 2));
            float m_new = fmaxf(m_i[eh], mloc);
            float alpha = __expf(m_i[eh] - m_new);

            float psum = 0.f;
            unsigned char* prow = fsm + FP_OFF + (wr + g + eh * 8) * FH_ROW;
            #pragma unroll
            for (int nt = 0; nt < 8; nt++) {
                float p0 = __expf(sacc[nt][eh * 2 + 0] - m_new);
                float p1 = __expf(sacc[nt][eh * 2 + 1] - m_new);
                psum += p0 + p1;
                *(__half2*)(prow + (nt * 8 + tg * 2) * 2) = __floats2half2_rn(p0, p1);
            }
            psum += __shfl_xor_sync(0xffffffffu, psum, 1);
            psum += __shfl_xor_sync(0xffffffffu, psum, 2);
            l_i[eh] = l_i[eh] * alpha + psum;
            m_i[eh] = m_new;
            #pragma unroll
            for (int nt = 0; nt < 8; nt++) {
                oacc[nt][eh * 2 + 0] *= alpha;
                oacc[nt][eh * 2 + 1] *= alpha;
            }
        }
        __syncwarp();   // Ps strip visible within warp

        // ---- O += P V : A = P (LDSM), B = V via ldmatrix.trans ----
        #pragma unroll
        for (int ks = 0; ks < 4; ks++) {
            unsigned int af[4], bf[8][2];
            LDSM_X4(af[0], af[1], af[2], af[3], p_addr + ks * 32);   // 16 keys = 32 B in P row
            #pragma unroll
            for (int p = 0; p < 4; p++) {
                LDSM_X4_T(bf[2*p][0], bf[2*p][1], bf[2*p+1][0], bf[2*p+1][1],
                          v_addr + ks * 16 * FH_ROW + p * 32);
            }
            #pragma unroll
            for (int nt = 0; nt < 8; nt++)
                MMA_F16(oacc[nt], af, bf[nt]);
        }
        __syncwarp();   // Ps reads done before next-iter overwrite
    }

    // ---- write O as half (consumed by fp16 projection GEMM) ----
    const int b_ = bh >> 4, hd = bh & 15;
    #pragma unroll
    for (int eh = 0; eh < 2; eh++) {
        int tok = q0g + wr + g + eh * 8;
        if (tok >= NN) continue;
        float inv = 1.f / l_i[eh];
        __half* o = g_attn_h + ((size_t)b_ * NN + tok) * CC + hd * DD;
        #pragma unroll
        for (int nt = 0; nt < 8; nt++) {
            __half2 hv = __floats2half2_rn(oacc[nt][eh * 2 + 0] * inv,
                                           oacc[nt][eh * 2 + 1] * inv);
            *(__half2*)(o + nt * 8 + tg * 2) = hv;
        }
    }
}

// ---------------------------------------------------------------------------
// CLS-row logits per (b,h): logits[m] = q0 . k[m] (fp32 path via g_q0/g_k32)
// ---------------------------------------------------------------------------
__global__ __launch_bounds__(128) void cls_logits_kernel()
{
    __shared__ float q0s[64];
    __shared__ float red[128];
    const int bh  = blockIdx.x;
    const int tid = threadIdx.x;
    const float* Kg = g_k32 + (size_t)bh * NN * DD;

    if (tid < 64) q0s[tid] = g_q0[bh * DD + tid];   // q already scaled
    __syncthreads();

    float lg[5];
    float mloc = -1e30f;
    #pragma unroll
    for (int i = 0; i < 5; i++) {
        int m = tid + i*128;
        float s = -1e30f;
        if (m < NN) {
            s = 0.f;
            const float* kr = Kg + (size_t)m * DD;
            #pragma unroll
            for (int d4 = 0; d4 < 64; d4 += 4) {
                float4 k4 = *(const float4*)(kr + d4);
                s += q0s[d4]*k4.x + q0s[d4+1]*k4.y + q0s[d4+2]*k4.z + q0s[d4+3]*k4.w;
            }
            g_cls_logits[(size_t)bh * NN + m] = s;
        }
        lg[i] = s;
        mloc = fmaxf(mloc, s);
    }

    red[tid] = mloc; __syncthreads();
    for (int o = 64; o > 0; o >>= 1) {
        if (tid < o) red[tid] = fmaxf(red[tid], red[tid+o]);
        __syncthreads();
    }
    float mx = red[0];
    __syncthreads();

    float se = 0.f;
    #pragma unroll
    for (int i = 0; i < 5; i++)
        if (lg[i] > -1e29f) se += __expf(lg[i] - mx);
    red[tid] = se; __syncthreads();
    for (int o = 64; o > 0; o >>= 1) {
        if (tid < o) red[tid] += red[tid+o];
        __syncthreads();
    }
    if (tid == 0) { g_cls_max[bh] = mx; g_cls_den[bh] = red[0]; }
}

// Head-mean of CLS logits and CLS attention
__global__ void cls_out_kernel(float* __restrict__ out_cta, float* __restrict__ out_ctl)
{
    int idx = blockIdx.x * blockDim.x + threadIdx.x;
    if (idx >= MTOK) return;
    int b_ = idx / NN;
    int m  = idx - b_ * NN;
    float sl = 0.f, sa = 0.f;
    #pragma unroll
    for (int h = 0; h < HH; h++) {
        int bh = b_ * HH + h;
        float l = g_cls_logits[(size_t)bh * NN + m];
        sl += l;
        sa += __expf(l - g_cls_max[bh]) / g_cls_den[bh];
    }
    out_ctl[idx] = sl * (1.f / 16.f);
    out_cta[idx] = sa * (1.f / 16.f);
}

// ---------------------------------------------------------------------------
extern "C" void kernel_launch(void* const* d_in, const int* in_sizes, int n_in,
                              void* d_out, int out_size)
{
    const float* x      = (const float*)d_in[0];
    const float* w_qkv  = (const float*)d_in[1];
    const float* b_qkv  = (const float*)d_in[2];
    const float* w_proj = (const float*)d_in[3];
    const float* b_proj = (const float*)d_in[4];
    float* out = (float*)d_out;

    cudaFuncSetAttribute(hgemm_nt,
                         cudaFuncAttributeMaxDynamicSharedMemorySize, HGEMM_SMEM);
    cudaFuncSetAttribute(flash_h_kernel,
                         cudaFuncAttributeMaxDynamicSharedMemorySize, FH_SMEM);

    // 0) Pre-round x / w_qkv / w_proj to half
    round_inputs_kernel<<<592, 256>>>(x, w_qkv, w_proj);

    // 1) QKV projection + scatter (q scaled) — fp16 m16n8k16 GEMM
    {
        dim3 grid(3*CC/128, (MTOK + 127) / 128);
        hgemm_nt<<<grid, 256, HGEMM_SMEM>>>(b_qkv, nullptr, MTOK, 3*CC, 1);
    }

    // 2) Flash attention — fp16 m16n8k16
    {
        dim3 grid(5, BB*HH);
        flash_h_kernel<<<grid, 256, FH_SMEM>>>();
    }

    // 3) CLS-row outputs (fp32 path)
    cls_logits_kernel<<<BB*HH, 128>>>();
    cls_out_kernel<<<(MTOK + 255) / 256, 256>>>(out + CTA_OFS, out + CTL_OFS);

    // 4) Output projection — fp16 m16n8k16 GEMM
    {
        dim3 grid(CC/128, (MTOK + 127) / 128);
        hgemm_nt<<<grid, 256, HGEMM_SMEM>>>(b_proj, out, MTOK, CC, 2);
    }
}

// round 16
// speedup vs baseline: 1.9378x; 1.0517x over previous
#include <cuda_runtime.h>
#include <cuda_fp16.h>
#include <math.h>

// Problem constants
#define BB 16
#define HH 16
#define NN 577
#define DD 64
#define CC 1024
#define MTOK (BB*NN)            // 9232
#define PLANE (BB*HH*NN*DD)     // 9,453,568 per q/k/v plane
#define OUT_ELEMS (MTOK*CC)     // 9,453,568
#define CTA_OFS OUT_ELEMS
#define CTL_OFS (OUT_ELEMS + MTOK)
#define QSCALE 0.125f           // 1/sqrt(64)
#define WQKV_ELEMS (3*CC*CC)    // 3,145,728
#define WPROJ_ELEMS (CC*CC)     // 1,048,576

// Scratch (device globals: allocation-free per harness rules)
__device__ __half g_qkv_h[3u * PLANE];    // [3][B][H][N][D] half (flash inputs)
__device__ float  g_k32[PLANE];           // K plane fp32 (CLS path)
__device__ float  g_q0[BB*HH*DD];         // q row-0 fp32 per (b,h) (CLS path)
__device__ __half g_attn_h[OUT_ELEMS];    // [B][N][C] attention output (half)
__device__ __half g_x_h[OUT_ELEMS];       // x rounded to half
__device__ __half g_wqkv_h[WQKV_ELEMS];   // w_qkv rounded to half
__device__ __half g_wproj_h[WPROJ_ELEMS]; // w_proj rounded to half
__device__ float  g_cls_logits[BB*HH*NN]; // per-head CLS-row logits (fp32)
__device__ float  g_cls_max[BB*HH];
__device__ float  g_cls_den[BB*HH];

#define MMA_F16(d, a, b) \
    asm("mma.sync.aligned.m16n8k16.row.col.f32.f16.f16.f32 " \
        "{%0,%1,%2,%3}, {%4,%5,%6,%7}, {%8,%9}, {%0,%1,%2,%3};" \
        : "+f"((d)[0]), "+f"((d)[1]), "+f"((d)[2]), "+f"((d)[3]) \
        : "r"((a)[0]), "r"((a)[1]), "r"((a)[2]), "r"((a)[3]), \
          "r"((b)[0]), "r"((b)[1]))

#define LDSM_X4(r0, r1, r2, r3, addr) \
    asm volatile("ldmatrix.sync.aligned.m8n8.x4.shared.b16 {%0,%1,%2,%3}, [%4];" \
        : "=r"(r0), "=r"(r1), "=r"(r2), "=r"(r3) : "r"(addr))

#define LDSM_X4_T(r0, r1, r2, r3, addr) \
    asm volatile("ldmatrix.sync.aligned.m8n8.x4.trans.shared.b16 {%0,%1,%2,%3}, [%4];" \
        : "=r"(r0), "=r"(r1), "=r"(r2), "=r"(r3) : "r"(addr))

#define CP_ASYNC16(smem_u32, gptr) \
    asm volatile("cp.async.cg.shared.global [%0], [%1], 16;" :: "r"(smem_u32), "l"(gptr) : "memory")
#define CP_COMMIT()  asm volatile("cp.async.commit_group;" ::: "memory")
#define CP_WAIT1()   asm volatile("cp.async.wait_group 1;" ::: "memory")
#define CP_WAIT0()   asm volatile("cp.async.wait_group 0;" ::: "memory")

// ---------------------------------------------------------------------------
// Pre-round inputs to half (one elementwise pass).
// ---------------------------------------------------------------------------
__global__ void round_inputs_kernel(const float* __restrict__ x,
                                    const float* __restrict__ wq,
                                    const float* __restrict__ wp)
{
    const int total = OUT_ELEMS + WQKV_ELEMS + WPROJ_ELEMS;
    for (int i = blockIdx.x * blockDim.x + threadIdx.x; i < total;
         i += gridDim.x * blockDim.x) {
        if (i < OUT_ELEMS) {
            g_x_h[i] = __float2half_rn(x[i]);
        } else if (i < OUT_ELEMS + WQKV_ELEMS) {
            int j = i - OUT_ELEMS;
            g_wqkv_h[j] = __float2half_rn(wq[j]);
        } else {
            int j = i - OUT_ELEMS - WQKV_ELEMS;
            g_wproj_h[j] = __float2half_rn(wp[j]);
        }
    }
}

// ---------------------------------------------------------------------------
// fp16 tensor-core GEMM (m16n8k16), cp.async double-buffered, ldmatrix.
// C[m,n] = sum_k A[m,k] * W[n,k] (+bias), fp32 accumulate. K = 1024.
// BM=BN=128, BK=64 halves (128 B/row data + 16 pad = 144 B -> all-bank LDSM).
// 16 k-iterations (half the barrier count of BK=32). 2 CTAs/SM pinned.
// mode 1: A=g_x_h, W=g_wqkv_h, scatter HALF into g_qkv_h (+ fp32 K plane/q0)
// mode 2: A=g_attn_h, W=g_wproj_h, plain epilogue into Cout
// ---------------------------------------------------------------------------
#define HROW_B   144
#define HTILE_B  (128 * HROW_B)          // 18432 B per operand tile
#define HGEMM_SMEM (4 * HTILE_B)         // 2 stages x (A + W) = 73728 B

__global__ void __launch_bounds__(256, 2) hgemm_nt(
    const float* __restrict__ bias, float* __restrict__ Cout,
    int M, int N, int mode)
{
    extern __shared__ unsigned char smraw[];
    const int K = 1024;
    const int NT = 16;                    // K / 64

    const __half* Abase = (mode == 2) ? g_attn_h : g_x_h;
    const __half* Wbase = (mode == 2) ? g_wproj_h : g_wqkv_h;

    const int tid  = threadIdx.x;
    const int lane = tid & 31;
    const int warp = tid >> 5;
    const int wm   = warp & 3;
    const int wn   = warp >> 2;
    const int bm   = blockIdx.y * 128;
    const int bn   = blockIdx.x * 128;

    float acc[2][8][4];
    #pragma unroll
    for (int i = 0; i < 2; i++)
        #pragma unroll
        for (int j = 0; j < 8; j++)
            #pragma unroll
            for (int e = 0; e < 4; e++) acc[i][j][e] = 0.f;

    const int g  = lane >> 2;
    const int tg = lane & 3;

    // cp.async coords: 128 rows x 8 chunks(16B) per operand = 1024; 4/thread
    unsigned int soff[4];
    const __half* aptr[4];
    const __half* wptr[4];
    #pragma unroll
    for (int i = 0; i < 4; i++) {
        int p   = i * 256 + tid;
        int row = p >> 3;
        int c16 = p & 7;
        soff[i] = (unsigned int)(row * HROW_B + c16 * 16);
        int ar  = bm + row;
        aptr[i] = Abase + (size_t)((ar < M) ? ar : (M - 1)) * K + c16 * 8;
        wptr[i] = Wbase + (size_t)(bn + row) * K + c16 * 8;
    }

    const unsigned int sbase = (unsigned int)__cvta_generic_to_shared(smraw);

    const int lrow16 = lane & 15;
    const int khalf  = (lane >> 4) * 16;
    const unsigned int a_off0 = (unsigned int)((wm * 32 +  0 + lrow16) * HROW_B + khalf);
    const unsigned int a_off1 = (unsigned int)((wm * 32 + 16 + lrow16) * HROW_B + khalf);
    unsigned int b_off[4];
    #pragma unroll
    for (int p = 0; p < 4; p++)
        b_off[p] = (unsigned int)((wn * 64 + p * 16 + lrow16) * HROW_B + khalf);

    // prologue: tile 0 -> stage 0
    {
        unsigned int as = sbase;
        unsigned int ws = sbase + HTILE_B;
        #pragma unroll
        for (int i = 0; i < 4; i++) {
            CP_ASYNC16(as + soff[i], aptr[i]);
            CP_ASYNC16(ws + soff[i], wptr[i]);
        }
        CP_COMMIT();
    }

    for (int t = 0; t < NT; t++) {
        const int s = t & 1;
        if (t + 1 < NT) {
            const int s2 = s ^ 1;
            const int k0 = (t + 1) * 64;
            unsigned int as = sbase + (unsigned)s2 * 2 * HTILE_B;
            unsigned int ws = as + HTILE_B;
            #pragma unroll
            for (int i = 0; i < 4; i++) {
                CP_ASYNC16(as + soff[i], aptr[i] + k0);
                CP_ASYNC16(ws + soff[i], wptr[i] + k0);
            }
            CP_COMMIT();
            CP_WAIT1();
        } else {
            CP_WAIT0();
        }
        __syncthreads();

        const unsigned int as_u32 = sbase + (unsigned)s * 2 * HTILE_B;
        const unsigned int ws_u32 = as_u32 + HTILE_B;

        #pragma unroll
        for (int ks = 0; ks < 4; ks++) {
            const int kb = ks * 32;      // 16 halves = 32 bytes per k16 step
            unsigned int af[2][4], bf[8][2];
            LDSM_X4(af[0][0], af[0][1], af[0][2], af[0][3], as_u32 + a_off0 + kb);
            LDSM_X4(af[1][0], af[1][1], af[1][2], af[1][3], as_u32 + a_off1 + kb);
            #pragma unroll
            for (int p = 0; p < 4; p++) {
                LDSM_X4(bf[2*p][0], bf[2*p+1][0], bf[2*p][1], bf[2*p+1][1],
                        ws_u32 + b_off[p] + kb);
            }
            #pragma unroll
            for (int mt = 0; mt < 2; mt++)
                #pragma unroll
                for (int nt = 0; nt < 8; nt++)
                    MMA_F16(acc[mt][nt], af[mt], bf[nt]);
        }
        __syncthreads();
    }

    #pragma unroll
    for (int mt = 0; mt < 2; mt++) {
        #pragma unroll
        for (int eh = 0; eh < 2; eh++) {
            int m = bm + wm * 32 + mt * 16 + g + eh * 8;
            if (m >= M) continue;
            if (mode == 1) {
                int b_  = m / NN;
                int tok = m - b_ * NN;
                #pragma unroll
                for (int nt = 0; nt < 8; nt++) {
                    #pragma unroll
                    for (int ec = 0; ec < 2; ec++) {
                        int n = bn + wn * 64 + nt * 8 + tg * 2 + ec;
                        float v = acc[mt][nt][eh * 2 + ec] + bias[n];
                        int which = n >> 10;
                        int rest  = n & 1023;
                        int h = rest >> 6;
                        int d = rest & 63;
                        if (which == 0) v *= QSCALE;
                        size_t idx = (((size_t)(b_ * HH + h) * NN + tok) << 6) + d;
                        g_qkv_h[(size_t)which * PLANE + idx] = __float2half_rn(v);
                        if (which == 1) g_k32[idx] = v;
                        else if (which == 0 && tok == 0) g_q0[(b_ * HH + h) * DD + d] = v;
                    }
                }
            } else {
                #pragma unroll
                for (int nt = 0; nt < 8; nt++) {
                    int n = bn + wn * 64 + nt * 8 + tg * 2;
                    float2 v = make_float2(acc[mt][nt][eh * 2 + 0] + bias[n],
                                           acc[mt][nt][eh * 2 + 1] + bias[n + 1]);
                    *(float2*)(Cout + (size_t)m * N + n) = v;
                }
            }
        }
    }
}

// ---------------------------------------------------------------------------
// fp16 tensor-core flash attention (m16n8k16).
// Grid (5 q-tiles of 128, 256 bh), 256 threads = 8 warps x 16 q-rows.
// smem rows 144 B. S = Q K^T, PV with V via ldmatrix.trans.
// ---------------------------------------------------------------------------
#define FH_ROW  144
#define FQ_OFF  0
#define FK_OFF  (128 * FH_ROW)
#define FV_OFF  (FK_OFF + 64 * FH_ROW)
#define FP_OFF  (FV_OFF + 64 * FH_ROW)
#define FH_SMEM (FP_OFF + 128 * FH_ROW)   // 55296 B

__global__ __launch_bounds__(256) void flash_h_kernel()
{
    extern __shared__ unsigned char fsm[];

    const int tid  = threadIdx.x;
    const int lane = tid & 31;
    const int warp = tid >> 5;
    const int g    = lane >> 2;
    const int tg   = lane & 3;
    const int qt   = blockIdx.x;          // 0..4
    const int bh   = blockIdx.y;          // 0..255
    const int q0g  = qt * 128;
    const int wr   = warp * 16;

    const __half* Qg = g_qkv_h + (size_t)bh * NN * DD;
    const __half* Kg = g_qkv_h + (size_t)PLANE + (size_t)bh * NN * DD;
    const __half* Vg = g_qkv_h + 2u * (size_t)PLANE + (size_t)bh * NN * DD;

    // Load Q tile: 128 rows x 8 chunks(16B) = 1024, 4 per thread.
    #pragma unroll
    for (int i = 0; i < 4; i++) {
        int p   = i * 256 + tid;
        int row = p >> 3;
        int c16 = p & 7;
        int tok = q0g + row; if (tok > NN - 1) tok = NN - 1;   // clamp (rows >= NN unused)
        *(uint4*)(fsm + FQ_OFF + row * FH_ROW + c16 * 16) =
            *(const uint4*)(Qg + (size_t)tok * DD + c16 * 8);
    }

    const unsigned int sb = (unsigned int)__cvta_generic_to_shared(fsm);
    const int lrow16 = lane & 15;
    const int kh16   = (lane >> 4) * 16;
    const unsigned int q_addr = sb + FQ_OFF + (unsigned)((wr + lrow16) * FH_ROW + kh16);
    const unsigned int p_addr = sb + FP_OFF + (unsigned)((wr + lrow16) * FH_ROW + kh16);
    const unsigned int k_addr = sb + FK_OFF + (unsigned)(lrow16 * FH_ROW + kh16);
    const int vrow = (lane & 7) + ((lane >> 3) & 1) * 8;
    const unsigned int v_addr = sb + FV_OFF + (unsigned)(vrow * FH_ROW + kh16);

    float oacc[8][4];
    #pragma unroll
    for (int nt = 0; nt < 8; nt++)
        #pragma unroll
        for (int e = 0; e < 4; e++) oacc[nt][e] = 0.f;
    float m_i[2] = { -1e30f, -1e30f };
    float l_i[2] = { 0.f, 0.f };

    for (int kt = 0; kt < 10; kt++) {
        const int k0g = kt * 64;
        __syncthreads();   // prior-iteration K/V reads complete (also covers Q store)

        // Load K/V tiles: 64 rows x 8 chunks each, 2+2 per thread.
        #pragma unroll
        for (int i = 0; i < 2; i++) {
            int p   = i * 256 + tid;
            int row = p >> 3;
            int c16 = p & 7;
            int tok = k0g + row; if (tok > NN - 1) tok = NN - 1;  // clamp (masked later)
            *(uint4*)(fsm + FK_OFF + row * FH_ROW + c16 * 16) =
                *(const uint4*)(Kg + (size_t)tok * DD + c16 * 8);
            *(uint4*)(fsm + FV_OFF + row * FH_ROW + c16 * 16) =
                *(const uint4*)(Vg + (size_t)tok * DD + c16 * 8);
        }
        __syncthreads();

        // ---- S = Q K^T : 16 q-rows x 64 keys per warp, 4 k16 steps ----
        float sacc[8][4];
        #pragma unroll
        for (int nt = 0; nt < 8; nt++)
            #pragma unroll
            for (int e = 0; e < 4; e++) sacc[nt][e] = 0.f;

        #pragma unroll
        for (int ks = 0; ks < 4; ks++) {
            const int kb = ks * 32;
            unsigned int af[4], bf[8][2];
            LDSM_X4(af[0], af[1], af[2], af[3], q_addr + kb);
            #pragma unroll
            for (int p = 0; p < 4; p++) {
                LDSM_X4(bf[2*p][0], bf[2*p+1][0], bf[2*p][1], bf[2*p+1][1],
                        k_addr + p * 16 * FH_ROW + kb);
            }
            #pragma unroll
            for (int nt = 0; nt < 8; nt++)
                MMA_F16(sacc[nt], af, bf[nt]);
        }

        // ---- online softmax on fragments (rows wr+g, wr+g+8) ----
        #pragma unroll
        for (int eh = 0; eh < 2; eh++) {
            float mloc = -1e30f;
            #pragma unroll
            for (int nt = 0; nt < 8; nt++) {
                #pragma unroll
                for (int ec = 0; ec < 2; ec++) {
                    int key = k0g + nt * 8 + tg * 2 + ec;
                    if (key >= NN) sacc[nt][eh * 2 + ec] = -1e30f;
                    mloc = fmaxf(mloc, sacc[nt][eh * 2 + ec]);
                }
            }
            mloc = fmaxf(mloc, __shfl_xor_sync(0xffffffffu, mloc, 1));
            mloc = fmaxf(mloc, __shfl_xor_sync(0xffffffffu, mloc, 2));
            float m_new = fmaxf(m_i[eh], mloc);
            float alpha = __expf(m_i[eh] - m_new);

            float psum = 0.f;
            unsigned char* prow = fsm + FP_OFF + (wr + g + eh * 8) * FH_ROW;
            #pragma unroll
            for (int nt = 0; nt < 8; nt++) {
                float p0 = __expf(sacc[nt][eh * 2 + 0] - m_new);
                float p1 = __expf(sacc[nt][eh * 2 + 1] - m_new);
                psum += p0 + p1;
                *(__half2*)(prow + (nt * 8 + tg * 2) * 2) = __floats2half2_rn(p0, p1);
            }
            psum += __shfl_xor_sync(0xffffffffu, psum, 1);
            psum += __shfl_xor_sync(0xffffffffu, psum, 2);
            l_i[eh] = l_i[eh] * alpha + psum;
            m_i[eh] = m_new;
            #pragma unroll
            for (int nt = 0; nt < 8; nt++) {
                oacc[nt][eh * 2 + 0] *= alpha;
                oacc[nt][eh * 2 + 1] *= alpha;
            }
        }
        __syncwarp();   // Ps strip visible within warp

        // ---- O += P V : A = P (LDSM), B = V via ldmatrix.trans ----
        #pragma unroll
        for (int ks = 0; ks < 4; ks++) {
            unsigned int af[4], bf[8][2];
            LDSM_X4(af[0], af[1], af[2], af[3], p_addr + ks * 32);
            #pragma unroll
            for (int p = 0; p < 4; p++) {
                LDSM_X4_T(bf[2*p][0], bf[2*p][1], bf[2*p+1][0], bf[2*p+1][1],
                          v_addr + ks * 16 * FH_ROW + p * 32);
            }
            #pragma unroll
            for (int nt = 0; nt < 8; nt++)
                MMA_F16(oacc[nt], af, bf[nt]);
        }
        __syncwarp();   // Ps reads done before next-iter overwrite
    }

    // ---- write O as half (consumed by fp16 projection GEMM) ----
    const int b_ = bh >> 4, hd = bh & 15;
    #pragma unroll
    for (int eh = 0; eh < 2; eh++) {
        int tok = q0g + wr + g + eh * 8;
        if (tok >= NN) continue;
        float inv = 1.f / l_i[eh];
        __half* o = g_attn_h + ((size_t)b_ * NN + tok) * CC + hd * DD;
        #pragma unroll
        for (int nt = 0; nt < 8; nt++) {
            __half2 hv = __floats2half2_rn(oacc[nt][eh * 2 + 0] * inv,
                                           oacc[nt][eh * 2 + 1] * inv);
            *(__half2*)(o + nt * 8 + tg * 2) = hv;
        }
    }
}

// ---------------------------------------------------------------------------
// CLS-row logits per (b,h): logits[m] = q0 . k[m] (fp32 path via g_q0/g_k32)
// ---------------------------------------------------------------------------
__global__ __launch_bounds__(128) void cls_logits_kernel()
{
    __shared__ float q0s[64];
    __shared__ float red[128];
    const int bh  = blockIdx.x;
    const int tid = threadIdx.x;
    const float* Kg = g_k32 + (size_t)bh * NN * DD;

    if (tid < 64) q0s[tid] = g_q0[bh * DD + tid];   // q already scaled
    __syncthreads();

    float lg[5];
    float mloc = -1e30f;
    #pragma unroll
    for (int i = 0; i < 5; i++) {
        int m = tid + i*128;
        float s = -1e30f;
        if (m < NN) {
            s = 0.f;
            const float* kr = Kg + (size_t)m * DD;
            #pragma unroll
            for (int d4 = 0; d4 < 64; d4 += 4) {
                float4 k4 = *(const float4*)(kr + d4);
                s += q0s[d4]*k4.x + q0s[d4+1]*k4.y + q0s[d4+2]*k4.z + q0s[d4+3]*k4.w;
            }
            g_cls_logits[(size_t)bh * NN + m] = s;
        }
        lg[i] = s;
        mloc = fmaxf(mloc, s);
    }

    red[tid] = mloc; __syncthreads();
    for (int o = 64; o > 0; o >>= 1) {
        if (tid < o) red[tid] = fmaxf(red[tid], red[tid+o]);
        __syncthreads();
    }
    float mx = red[0];
    __syncthreads();

    float se = 0.f;
    #pragma unroll
    for (int i = 0; i < 5; i++)
        if (lg[i] > -1e29f) se += __expf(lg[i] - mx);
    red[tid] = se; __syncthreads();
    for (int o = 64; o > 0; o >>= 1) {
        if (tid < o) red[tid] += red[tid+o];
        __syncthreads();
    }
    if (tid == 0) { g_cls_max[bh] = mx; g_cls_den[bh] = red[0]; }
}

// Head-mean of CLS logits and CLS attention
__global__ void cls_out_kernel(float* __restrict__ out_cta, float* __restrict__ out_ctl)
{
    int idx = blockIdx.x * blockDim.x + threadIdx.x;
    if (idx >= MTOK) return;
    int b_ = idx / NN;
    int m  = idx - b_ * NN;
    float sl = 0.f, sa = 0.f;
    #pragma unroll
    for (int h = 0; h < HH; h++) {
        int bh = b_ * HH + h;
        float l = g_cls_logits[(size_t)bh * NN + m];
        sl += l;
        sa += __expf(l - g_cls_max[bh]) / g_cls_den[bh];
    }
    out_ctl[idx] = sl * (1.f / 16.f);
    out_cta[idx] = sa * (1.f / 16.f);
}

// ---------------------------------------------------------------------------
extern "C" void kernel_launch(void* const* d_in, const int* in_sizes, int n_in,
                              void* d_out, int out_size)
{
    const float* x      = (const float*)d_in[0];
    const float* w_qkv  = (const float*)d_in[1];
    const float* b_qkv  = (const float*)d_in[2];
    const float* w_proj = (const float*)d_in[3];
    const float* b_proj = (const float*)d_in[4];
    float* out = (float*)d_out;

    cudaFuncSetAttribute(hgemm_nt,
                         cudaFuncAttributeMaxDynamicSharedMemorySize, HGEMM_SMEM);
    cudaFuncSetAttribute(flash_h_kernel,
                         cudaFuncAttributeMaxDynamicSharedMemorySize, FH_SMEM);

    // 0) Pre-round x / w_qkv / w_proj to half
    round_inputs_kernel<<<592, 256>>>(x, w_qkv, w_proj);

    // 1) QKV projection + scatter (q scaled) — fp16 m16n8k16 GEMM, BK=64
    {
        dim3 grid(3*CC/128, (MTOK + 127) / 128);
        hgemm_nt<<<grid, 256, HGEMM_SMEM>>>(b_qkv, nullptr, MTOK, 3*CC, 1);
    }

    // 2) Flash attention — fp16 m16n8k16
    {
        dim3 grid(5, BB*HH);
        flash_h_kernel<<<grid, 256, FH_SMEM>>>();
    }

    // 3) CLS-row outputs (fp32 path)
    cls_logits_kernel<<<BB*HH, 128>>>();
    cls_out_kernel<<<(MTOK + 255) / 256, 256>>>(out + CTA_OFS, out + CTL_OFS);

    // 4) Output projection — fp16 m16n8k16 GEMM, BK=64
    {
        dim3 grid(CC/128, (MTOK + 127) / 128);
        hgemm_nt<<<grid, 256, HGEMM_SMEM>>>(b_proj, out, MTOK, CC, 2);
    }
}